// round 12
// baseline (speedup 1.0000x reference)
#include <cuda_runtime.h>
#include <cuda_fp16.h>
#include <cstddef>
#include <cstdint>

#define NN 100000
#define NE 1000000
#define DD 300
#define MP 100096      // NN padded to 64
#define KP1 320        // K=300 padded
#define NP  320        // N=300 padded
#define KPM 640        // merge K=600 padded

typedef __half fp16;
typedef __half2 fp162;

// ---------------- scratch (device globals; no allocation allowed) ----------
__device__ int   g_ideg[4 * NN];
__device__ float g_deg[4 * NN];
__device__ int   g_off_r[NN + 1], g_off_c[NN + 1];
__device__ int   g_cur_r[NN],     g_cur_c[NN];
__device__ int   g_csr_r[NE],     g_csr_c[NE];

#define SB 1024
#define NSB ((NN + SB - 1) / SB)   // 98
__device__ int g_bsum[2][NSB];
__device__ int g_boff[2][NSB];

// fp16 feature table (NN x DD)
__device__ __align__(16) fp16 g_xh[(size_t)NN * DD];
// fp16 operand planes (padded, M x K row-major)
__device__ __align__(16) fp16 g_aggr[(size_t)MP * KP1];
__device__ __align__(16) fp16 g_aggc[(size_t)MP * KP1];
__device__ __align__(16) fp16 g_rowg[(size_t)MP * KP1];
__device__ __align__(16) fp16 g_colg[(size_t)MP * KP1];
__device__ __align__(16) fp16 g_mrg[(size_t)MP * KPM];
// weight planes (fp16): K x N row-major
__device__ __align__(16) fp16 g_Wr[KP1 * NP];
__device__ __align__(16) fp16 g_Wc[KP1 * NP];
__device__ __align__(16) fp16 g_Wrs[KP1 * NP];
__device__ __align__(16) fp16 g_Wcs[KP1 * NP];
__device__ __align__(16) fp16 g_Wm[KPM * NP];

// ---------------- helpers ----------------------------------------------------
__device__ __forceinline__ uint32_t pack2(fp16 a, fp16 b) {
    fp162 t = __halves2half2(a, b);
    return *(uint32_t*)&t;
}
#define SWZ(x) ((x) ^ (((x) >> 3) & 0x70))
__device__ __forceinline__ void cp16(uint32_t dst, const void* src) {
    asm volatile("cp.async.cg.shared.global [%0], [%1], 16;" :: "r"(dst), "l"(src));
}
__device__ __forceinline__ void ldsm_x4(uint32_t& r0, uint32_t& r1, uint32_t& r2, uint32_t& r3,
                                        uint32_t addr) {
    asm volatile("ldmatrix.sync.aligned.m8n8.x4.shared.b16 {%0,%1,%2,%3}, [%4];"
                 : "=r"(r0), "=r"(r1), "=r"(r2), "=r"(r3) : "r"(addr));
}
__device__ __forceinline__ void ldsm_x4_t(uint32_t& r0, uint32_t& r1, uint32_t& r2, uint32_t& r3,
                                          uint32_t addr) {
    asm volatile("ldmatrix.sync.aligned.m8n8.x4.trans.shared.b16 {%0,%1,%2,%3}, [%4];"
                 : "=r"(r0), "=r"(r1), "=r"(r2), "=r"(r3) : "r"(addr));
}
__device__ __forceinline__ void mma_fp16(float* c, const uint32_t* a, const uint32_t* b) {
    asm volatile("mma.sync.aligned.m16n8k16.row.col.f32.f16.f16.f32 "
                 "{%0,%1,%2,%3}, {%4,%5,%6,%7}, {%8,%9}, {%0,%1,%2,%3};"
                 : "+f"(c[0]), "+f"(c[1]), "+f"(c[2]), "+f"(c[3])
                 : "r"(a[0]), "r"(a[1]), "r"(a[2]), "r"(a[3]), "r"(b[0]), "r"(b[1]));
}

// ---------------- graph preprocessing ----------------------------------------
__global__ void zero_ideg_kernel() {
    int i = blockIdx.x * blockDim.x + threadIdx.x;
    if (i < 4 * NN) g_ideg[i] = 0;
}

__global__ void degree_kernel(const int* __restrict__ er, const int* __restrict__ ec) {
    int i = blockIdx.x * blockDim.x + threadIdx.x;
    if (i < NE) {
        atomicAdd(&g_ideg[0 * NN + er[i]],      1);
        atomicAdd(&g_ideg[1 * NN + er[NE + i]], 1);
        atomicAdd(&g_ideg[2 * NN + ec[i]],      1);
        atomicAdd(&g_ideg[3 * NN + ec[NE + i]], 1);
    }
}

__global__ void norm_kernel() {
    int i = blockIdx.x * blockDim.x + threadIdx.x;
    if (i < 4 * NN) {
        int d = g_ideg[i];
        g_deg[i] = (d > 0) ? rsqrtf((float)d) : 0.f;
    }
}

__global__ void x_convert_kernel(const float2* __restrict__ x) {
    long i = (long)blockIdx.x * blockDim.x + threadIdx.x;
    if (i < (long)NN * DD / 2) {
        float2 v = x[i];
        *(uint32_t*)&g_xh[i * 2] = pack2(__float2half(v.x), __float2half(v.y));
    }
}

__global__ __launch_bounds__(SB) void scan1_kernel() {
    int gsel = blockIdx.y;
    const int* deg = g_ideg + (gsel ? 3 : 1) * NN;
    int i = blockIdx.x * SB + threadIdx.x;
    int v = (i < NN) ? deg[i] : 0;
    __shared__ int ws[32];
    #pragma unroll
    for (int o = 16; o > 0; o >>= 1) v += __shfl_xor_sync(0xFFFFFFFFu, v, o);
    if ((threadIdx.x & 31) == 0) ws[threadIdx.x >> 5] = v;
    __syncthreads();
    if (threadIdx.x < 32) {
        int s = (threadIdx.x < SB / 32) ? ws[threadIdx.x] : 0;
        #pragma unroll
        for (int o = 16; o > 0; o >>= 1) s += __shfl_xor_sync(0xFFFFFFFFu, s, o);
        if (threadIdx.x == 0) g_bsum[gsel][blockIdx.x] = s;
    }
}

__global__ __launch_bounds__(256) void scan2_kernel(int* __restrict__ off_r,
                                                    int* __restrict__ off_c) {
    __shared__ int ss[2][128];
    int t = threadIdx.x;
    int h = t >> 7;
    int j = t & 127;
    int v = (j < NSB) ? g_bsum[h][j] : 0;
    ss[h][j] = v;
    __syncthreads();
    #pragma unroll
    for (int d = 1; d < 128; d <<= 1) {
        int u = (j >= d) ? ss[h][j - d] : 0;
        __syncthreads();
        ss[h][j] += u;
        __syncthreads();
    }
    if (j < NSB) g_boff[h][j] = ss[h][j] - v;
    if (t == 0) { off_r[NN] = NE; off_c[NN] = NE; }
}

__global__ __launch_bounds__(SB) void scan3_kernel(int* __restrict__ off_r,
                                                   int* __restrict__ cur_r,
                                                   int* __restrict__ off_c,
                                                   int* __restrict__ cur_c) {
    int gsel = blockIdx.y;
    const int* deg = g_ideg + (gsel ? 3 : 1) * NN;
    int* off = gsel ? off_c : off_r;
    int* cur = gsel ? cur_c : cur_r;
    __shared__ int ss[SB];
    int i = blockIdx.x * SB + threadIdx.x;
    int v = (i < NN) ? deg[i] : 0;
    ss[threadIdx.x] = v;
    __syncthreads();
    #pragma unroll
    for (int d = 1; d < SB; d <<= 1) {
        int u = (threadIdx.x >= d) ? ss[threadIdx.x - d] : 0;
        __syncthreads();
        ss[threadIdx.x] += u;
        __syncthreads();
    }
    if (i < NN) {
        int excl = ss[threadIdx.x] - v + g_boff[gsel][blockIdx.x];
        off[i] = excl;
        cur[i] = excl;
    }
}

__global__ void fill_kernel(const int* __restrict__ edges,
                            int* __restrict__ cur, int* __restrict__ csr) {
    int i = blockIdx.x * blockDim.x + threadIdx.x;
    if (i < NE) {
        int s = edges[i];
        int d = edges[NE + i];
        int pos = atomicAdd(&cur[d], 1);
        csr[pos] = s;
    }
}

// one warp per node; fp16 x reads, fp32 accumulate, 2-edge unroll
__global__ __launch_bounds__(256) void gather_kernel(
    const int* __restrict__ csr, const int* __restrict__ off,
    const float* __restrict__ nsrc, const float* __restrict__ ndst,
    fp16* __restrict__ Ah) {
    int warp = (int)((blockIdx.x * (long)blockDim.x + threadIdx.x) >> 5);
    int lane = threadIdx.x & 31;
    if (warp >= NN) return;
    int o0 = off[warp], o1 = off[warp + 1];
    float4 a0 = make_float4(0.f, 0.f, 0.f, 0.f);
    float4 a1 = a0, a2 = a0;
    auto accum = [&](int s, float ns) {
        const uint2* xr = (const uint2*)(g_xh + (size_t)s * DD);
        uint2 u = xr[lane];
        float2 p0 = __half22float2(*(fp162*)&u.x);
        float2 p1 = __half22float2(*(fp162*)&u.y);
        a0.x += p0.x * ns; a0.y += p0.y * ns; a0.z += p1.x * ns; a0.w += p1.y * ns;
        u = xr[32 + lane];
        p0 = __half22float2(*(fp162*)&u.x);
        p1 = __half22float2(*(fp162*)&u.y);
        a1.x += p0.x * ns; a1.y += p0.y * ns; a1.z += p1.x * ns; a1.w += p1.y * ns;
        if (lane < 11) {
            u = xr[64 + lane];
            p0 = __half22float2(*(fp162*)&u.x);
            p1 = __half22float2(*(fp162*)&u.y);
            a2.x += p0.x * ns; a2.y += p0.y * ns; a2.z += p1.x * ns; a2.w += p1.y * ns;
        }
    };
    int j = o0;
    for (; j + 1 < o1; j += 2) {
        int s0 = csr[j], s1 = csr[j + 1];
        float ns0 = nsrc[s0], ns1 = nsrc[s1];
        accum(s0, ns0);
        accum(s1, ns1);
    }
    if (j < o1) {
        int s0 = csr[j];
        accum(s0, nsrc[s0]);
    }
    float nd = ndst[warp];
    size_t orow = (size_t)warp * KP1;
    auto store4 = [&](float4 a, int f4i) {
        uint2 hh = make_uint2(
            pack2(__float2half(a.x * nd), __float2half(a.y * nd)),
            pack2(__float2half(a.z * nd), __float2half(a.w * nd)));
        *(uint2*)&Ah[orow + f4i * 4] = hh;
    };
    store4(a0, lane);
    store4(a1, 32 + lane);
    if (lane < 11) store4(a2, 64 + lane);
    if (lane < 20) Ah[orow + 300 + lane] = __float2half(0.f);
}

// zero tail rows [NN, MP) of agg + mrg planes
__global__ void tail_zero_kernel() {
    int i = blockIdx.x * blockDim.x + threadIdx.x;
    const int nAgg = (MP - NN) * KP1;
    const int nMrg = (MP - NN) * KPM;
    fp16 z = __float2half(0.f);
    if (i < nAgg) {
        size_t o = (size_t)NN * KP1 + i;
        g_aggr[o] = z;
        g_aggc[o] = z;
    }
    if (i < nMrg) g_mrg[(size_t)NN * KPM + i] = z;
}

// zero mrg pad cols [600,640) for valid rows
__global__ void pad_zero_kernel() {
    long i = (long)blockIdx.x * blockDim.x + threadIdx.x;
    if (i < (long)NN * 40) {
        int row = (int)(i / 40);
        int c = (int)(i - (long)row * 40);
        g_mrg[(size_t)row * KPM + 600 + c] = __float2half(0.f);
    }
}

// weight (K x Ncols fp32) -> fp16 plane (KPp x NP), zero padded
__global__ void w_convert_kernel(const float* __restrict__ W, int K, int Ncols, int KPp,
                                 fp16* __restrict__ Wh) {
    int idx = blockIdx.x * blockDim.x + threadIdx.x;
    if (idx >= KPp * NP) return;
    int k = idx / NP;
    int n = idx - k * NP;
    float v = (k < K && n < Ncols) ? W[(size_t)k * Ncols + n] : 0.f;
    Wh[idx] = __float2half(v);
}

// ===== Tensor-core GEMM: M=64 x N=320 per CTA, 512 thr, fused LN epilogues ==
// mode 1: relu -> fp16 plane, full padded tile (zeros OOB)
// mode 2: +bias -> LayerNorm -> fp16 store (valid only) to Ch
// mode 3: +bias -> LayerNorm -> fp32 store (valid only) to Cf
#define GBM 64
#define GBK 64
#define A_PL 8192u                  // 64 rows x 128B
#define B_PL 40960u                 // 5 subtiles x 64 rows x 128B
#define STG (A_PL + B_PL)           // 49152
#define PAR_OFF (2 * STG)           // params after stages
#define RED_OFF (PAR_OFF + 3 * 320 * 4)
#define SMEM_GEMM (RED_OFF + 64 * 4 * 8)   // + red[64][4] float2 = 104192

__global__ __launch_bounds__(512) void gemm_ln_kernel(
    const fp16* __restrict__ Ap, int lda,
    const fp16* __restrict__ Bp,
    const float* __restrict__ bias,
    const float* __restrict__ gamma, const float* __restrict__ beta,
    int M, int Ncols, int nK, int mode,
    float* __restrict__ Cf, int ldc,
    fp16* __restrict__ Ch, int ldcp)
{
    extern __shared__ __align__(128) char smem[];
    const uint32_t sb = (uint32_t)__cvta_generic_to_shared(smem);
    float* sBias  = (float*)(smem + PAR_OFF);
    float* sGamma = sBias + 320;
    float* sBeta  = sGamma + 320;
    float2* sRed  = (float2*)(smem + RED_OFF);

    const int t = threadIdx.x;
    const int wid = t >> 5;
    const int lane = t & 31;
    const int warp_m = wid >> 2;      // 0..3 -> 16-row strips
    const int warp_n = wid & 3;       // 0..3 -> 16-col strided strips
    const int m0 = blockIdx.x * GBM;

    // load params
    for (int i = t; i < 320; i += 512) {
        sBias[i] = (bias != nullptr && i < Ncols) ? bias[i] : 0.f;
        if (mode >= 2) {
            sGamma[i] = (i < Ncols) ? gamma[i] : 0.f;
            sBeta[i]  = (i < Ncols) ? beta[i]  : 0.f;
        }
    }

    float acc[10][4];
    #pragma unroll
    for (int ni = 0; ni < 10; ni++)
        #pragma unroll
        for (int j = 0; j < 4; j++) acc[ni][j] = 0.f;

    // loader: A 512 chunks (1/thread), B 2560 chunks (5/thread)
    const int ar = t >> 3, ac = t & 7;
    auto load_stage = [&](int stage, int k0) {
        const uint32_t base = sb + (uint32_t)stage * STG;
        cp16(base + SWZ((uint32_t)(ar * 128 + ac * 16)),
             Ap + (size_t)(m0 + ar) * lda + k0 + ac * 8);
        const uint32_t aB = base + A_PL;
        #pragma unroll
        for (int i = 0; i < 5; i++) {
            uint32_t d = aB + i * 8192u + SWZ((uint32_t)(ar * 128 + ac * 16));
            cp16(d, Bp + (size_t)(k0 + ar) * NP + i * 64 + ac * 8);
        }
        asm volatile("cp.async.commit_group;");
    };

    load_stage(0, 0);

    const int lrow = lane & 15;
    const int lhi = lane >> 4;

    for (int kt = 0; kt < nK; kt++) {
        if (kt + 1 < nK) {
            load_stage((kt + 1) & 1, (kt + 1) * GBK);
            asm volatile("cp.async.wait_group 1;");
        } else {
            asm volatile("cp.async.wait_group 0;");
        }
        __syncthreads();

        const uint32_t base = sb + (uint32_t)(kt & 1) * STG;
        const uint32_t aA = base;
        const uint32_t aB = base + A_PL;

        #pragma unroll
        for (int ks = 0; ks < 4; ks++) {
            uint32_t a[4];
            {
                int row = warp_m * 16 + lrow;
                uint32_t off = SWZ((uint32_t)(row * 128 + ks * 32 + lhi * 16));
                ldsm_x4(a[0], a[1], a[2], a[3], aA + off);
            }
            #pragma unroll
            for (int s = 0; s < 5; s++) {
                int krow = ks * 16 + lrow;
                uint32_t off = (uint32_t)s * 8192u
                             + SWZ((uint32_t)(krow * 128 + warp_n * 32 + lhi * 16));
                uint32_t r0, r1, r2, r3;
                ldsm_x4_t(r0, r1, r2, r3, aB + off);
                uint32_t b0[2] = { r0, r1 };
                uint32_t b1[2] = { r2, r3 };
                mma_fp16(acc[s * 2 + 0], a, b0);
                mma_fp16(acc[s * 2 + 1], a, b1);
            }
        }
        __syncthreads();
    }

    // ---- epilogue ----
    const int g = lane >> 2;
    const int tig = lane & 3;
    const int lrow0 = warp_m * 16 + g;       // local rows lrow0, lrow0+8

    if (mode == 1) {
        #pragma unroll
        for (int ni = 0; ni < 10; ni++) {
            int col = (ni >> 1) * 64 + warp_n * 16 + (ni & 1) * 8 + tig * 2;
            float bx = sBias[col], by = sBias[col + 1];
            #pragma unroll
            for (int rr = 0; rr < 2; rr++) {
                int row = m0 + lrow0 + rr * 8;
                float vx = fmaxf(acc[ni][rr * 2 + 0] + bx, 0.f);
                float vy = fmaxf(acc[ni][rr * 2 + 1] + by, 0.f);
                if (row >= M || col >= Ncols) { vx = 0.f; vy = 0.f; }
                *(uint32_t*)&Ch[(size_t)row * ldcp + col] =
                    pack2(__float2half(vx), __float2half(vy));
            }
        }
        return;
    }

    // modes 2/3: add bias, then LayerNorm over the full row (Ncols valid)
    float sum[2] = {0.f, 0.f}, sq[2] = {0.f, 0.f};
    #pragma unroll
    for (int ni = 0; ni < 10; ni++) {
        int col = (ni >> 1) * 64 + warp_n * 16 + (ni & 1) * 8 + tig * 2;
        acc[ni][0] += sBias[col];     acc[ni][1] += sBias[col + 1];
        acc[ni][2] += sBias[col];     acc[ni][3] += sBias[col + 1];
        sum[0] += acc[ni][0] + acc[ni][1];
        sum[1] += acc[ni][2] + acc[ni][3];
        sq[0]  += acc[ni][0] * acc[ni][0] + acc[ni][1] * acc[ni][1];
        sq[1]  += acc[ni][2] * acc[ni][2] + acc[ni][3] * acc[ni][3];
    }
    // reduce across the 4 lanes sharing each row
    #pragma unroll
    for (int o = 1; o <= 2; o <<= 1) {
        sum[0] += __shfl_xor_sync(0xFFFFFFFFu, sum[0], o);
        sum[1] += __shfl_xor_sync(0xFFFFFFFFu, sum[1], o);
        sq[0]  += __shfl_xor_sync(0xFFFFFFFFu, sq[0], o);
        sq[1]  += __shfl_xor_sync(0xFFFFFFFFu, sq[1], o);
    }
    if (tig == 0) {
        sRed[(lrow0)     * 4 + warp_n] = make_float2(sum[0], sq[0]);
        sRed[(lrow0 + 8) * 4 + warp_n] = make_float2(sum[1], sq[1]);
    }
    __syncthreads();
    float mu[2], rsig[2];
    #pragma unroll
    for (int rr = 0; rr < 2; rr++) {
        int lr = lrow0 + rr * 8;
        float2 p0 = sRed[lr * 4 + 0], p1 = sRed[lr * 4 + 1];
        float2 p2 = sRed[lr * 4 + 2], p3 = sRed[lr * 4 + 3];
        float s = p0.x + p1.x + p2.x + p3.x;
        float q = p0.y + p1.y + p2.y + p3.y;
        float m = s / (float)Ncols;
        float var = q / (float)Ncols - m * m;
        mu[rr] = m;
        rsig[rr] = rsqrtf(fmaxf(var, 0.f) + 1e-5f);
    }
    #pragma unroll
    for (int ni = 0; ni < 10; ni++) {
        int col = (ni >> 1) * 64 + warp_n * 16 + (ni & 1) * 8 + tig * 2;
        if (col >= Ncols) continue;
        float gx = sGamma[col], gy = sGamma[col + 1];
        float bx = sBeta[col],  by = sBeta[col + 1];
        #pragma unroll
        for (int rr = 0; rr < 2; rr++) {
            int row = m0 + lrow0 + rr * 8;
            if (row >= M) continue;
            float vx = (acc[ni][rr * 2 + 0] - mu[rr]) * rsig[rr] * gx + bx;
            float vy = (acc[ni][rr * 2 + 1] - mu[rr]) * rsig[rr] * gy + by;
            if (mode == 2) {
                *(uint32_t*)&Ch[(size_t)row * ldcp + col] =
                    pack2(__float2half(vx), __float2half(vy));
            } else {
                *(float2*)(Cf + (size_t)row * ldc + col) = make_float2(vx, vy);
            }
        }
    }
}

// ---------------- launch ----------------------------------------------------
extern "C" void kernel_launch(void* const* d_in, const int* in_sizes, int n_in,
                              void* d_out, int out_size) {
    const float* x    = (const float*)d_in[0];
    const int*   er   = (const int*)d_in[1];
    const int*   ec   = (const int*)d_in[2];
    const float* Wr   = (const float*)d_in[3];
    const float* br   = (const float*)d_in[4];
    const float* Wc   = (const float*)d_in[5];
    const float* bc   = (const float*)d_in[6];
    const float* Wrs  = (const float*)d_in[7];
    const float* brs  = (const float*)d_in[8];
    const float* g_rs = (const float*)d_in[9];
    const float* b_rs = (const float*)d_in[10];
    const float* Wcs  = (const float*)d_in[11];
    const float* bcs  = (const float*)d_in[12];
    const float* g_cs = (const float*)d_in[13];
    const float* b_cs = (const float*)d_in[14];
    const float* Wm   = (const float*)d_in[15];
    const float* bm   = (const float*)d_in[16];
    const float* g_m  = (const float*)d_in[17];
    const float* b_m  = (const float*)d_in[18];
    float* out = (float*)d_out;

    float* deg;
    cudaGetSymbolAddress((void**)&deg, g_deg);
    int *off_r, *off_c, *cur_r, *cur_c, *csr_r, *csr_c;
    cudaGetSymbolAddress((void**)&off_r, g_off_r);
    cudaGetSymbolAddress((void**)&off_c, g_off_c);
    cudaGetSymbolAddress((void**)&cur_r, g_cur_r);
    cudaGetSymbolAddress((void**)&cur_c, g_cur_c);
    cudaGetSymbolAddress((void**)&csr_r, g_csr_r);
    cudaGetSymbolAddress((void**)&csr_c, g_csr_c);

    fp16 *aggr, *aggc, *rowg, *colg, *mrg;
    fp16 *pWr, *pWc, *pWrs, *pWcs, *pWm;
    cudaGetSymbolAddress((void**)&aggr, g_aggr);
    cudaGetSymbolAddress((void**)&aggc, g_aggc);
    cudaGetSymbolAddress((void**)&rowg, g_rowg);
    cudaGetSymbolAddress((void**)&colg, g_colg);
    cudaGetSymbolAddress((void**)&mrg,  g_mrg);
    cudaGetSymbolAddress((void**)&pWr,  g_Wr);
    cudaGetSymbolAddress((void**)&pWc,  g_Wc);
    cudaGetSymbolAddress((void**)&pWrs, g_Wrs);
    cudaGetSymbolAddress((void**)&pWcs, g_Wcs);
    cudaGetSymbolAddress((void**)&pWm,  g_Wm);

    cudaFuncSetAttribute(gemm_ln_kernel,
                         cudaFuncAttributeMaxDynamicSharedMemorySize, SMEM_GEMM);

    // graph preprocessing (ordered so ncu -s5 captures fill_kernel)
    zero_ideg_kernel<<<(4 * NN + 255) / 256, 256>>>();
    degree_kernel<<<(NE + 255) / 256, 256>>>(er, ec);
    dim3 sgrid(NSB, 2);
    scan1_kernel<<<sgrid, SB>>>();
    scan2_kernel<<<1, 256>>>(off_r, off_c);
    scan3_kernel<<<sgrid, SB>>>(off_r, cur_r, off_c, cur_c);
    fill_kernel<<<(NE + 255) / 256, 256>>>(er, cur_r, csr_r);
    fill_kernel<<<(NE + 255) / 256, 256>>>(ec, cur_c, csr_c);
    norm_kernel<<<(4 * NN + 255) / 256, 256>>>();
    x_convert_kernel<<<(int)(((long)NN * DD / 2 + 255) / 256), 256>>>((const float2*)x);
    int ggrid = (NN * 32 + 255) / 256;
    gather_kernel<<<ggrid, 256>>>(csr_r, off_r, deg + 0 * NN, deg + 1 * NN, aggr);
    gather_kernel<<<ggrid, 256>>>(csr_c, off_c, deg + 2 * NN, deg + 3 * NN, aggc);
    tail_zero_kernel<<<((MP - NN) * KPM + 255) / 256, 256>>>();
    pad_zero_kernel<<<(int)(((long)NN * 40 + 255) / 256), 256>>>();

    // weight converts
    int wgrid = (KP1 * NP + 255) / 256;
    w_convert_kernel<<<wgrid, 256>>>(Wr,  DD, DD, KP1, pWr);
    w_convert_kernel<<<wgrid, 256>>>(Wc,  DD, DD, KP1, pWc);
    w_convert_kernel<<<wgrid, 256>>>(Wrs, DD, DD, KP1, pWrs);
    w_convert_kernel<<<wgrid, 256>>>(Wcs, DD, DD, KP1, pWcs);
    w_convert_kernel<<<(KPM * NP + 255) / 256, 256>>>(Wm, 2 * DD, DD, KPM, pWm);

    const int GG = MP / GBM;       // 1564
    const int nK1 = KP1 / GBK;     // 5
    const int nKm = KPM / GBK;     // 10

    // GraphConv GEMMs: relu -> fp16 planes
    gemm_ln_kernel<<<GG, 512, SMEM_GEMM>>>(aggr, KP1, pWr, br, nullptr, nullptr,
        NN, DD, nK1, 1, nullptr, 0, rowg, KP1);
    gemm_ln_kernel<<<GG, 512, SMEM_GEMM>>>(aggc, KP1, pWc, bc, nullptr, nullptr,
        NN, DD, nK1, 1, nullptr, 0, colg, KP1);

    // support GEMMs: bias + LayerNorm fused -> fp16 mrg halves
    gemm_ln_kernel<<<GG, 512, SMEM_GEMM>>>(rowg, KP1, pWrs, brs, g_rs, b_rs,
        NN, DD, nK1, 2, nullptr, 0, mrg, KPM);
    gemm_ln_kernel<<<GG, 512, SMEM_GEMM>>>(colg, KP1, pWcs, bcs, g_cs, b_cs,
        NN, DD, nK1, 2, nullptr, 0, mrg + DD, KPM);

    // merge GEMM (K=640): bias + final LayerNorm fused -> fp32 out
    gemm_ln_kernel<<<GG, 512, SMEM_GEMM>>>(mrg, KPM, pWm, bm, g_m, b_m,
        NN, DD, nKm, 3, out, DD, nullptr, 0);
}

// round 13
// speedup vs baseline: 1.0349x; 1.0349x over previous
#include <cuda_runtime.h>
#include <cuda_fp16.h>
#include <cstddef>
#include <cstdint>

#define NN 100000
#define NE 1000000
#define DD 300
#define MP 100096      // NN padded to 128
#define KP1 320        // K=300 padded
#define NP  320        // N=300 padded
#define KPM 640        // merge K=600 padded

typedef __half fp16;
typedef __half2 fp162;

// ---------------- scratch (device globals; no allocation allowed) ----------
__device__ int   g_ideg[4 * NN];
__device__ float g_deg[4 * NN];
__device__ int   g_off_r[NN + 1], g_off_c[NN + 1];
__device__ int   g_cur_r[NN],     g_cur_c[NN];
__device__ int   g_csr_r[NE],     g_csr_c[NE];

#define SB 1024
#define NSB ((NN + SB - 1) / SB)   // 98
__device__ int g_bsum[2][NSB];
__device__ int g_boff[2][NSB];

// fp16 feature table (NN x DD)
__device__ __align__(16) fp16 g_xh[(size_t)NN * DD];
// fp16 operand planes (padded, M x K row-major)
__device__ __align__(16) fp16 g_aggr[(size_t)MP * KP1];
__device__ __align__(16) fp16 g_aggc[(size_t)MP * KP1];
__device__ __align__(16) fp16 g_rowg[(size_t)MP * KP1];
__device__ __align__(16) fp16 g_colg[(size_t)MP * KP1];
__device__ __align__(16) fp16 g_mrg[(size_t)MP * KPM];
// weight planes (single fp16): K x N row-major
__device__ __align__(16) fp16 g_Wr[KP1 * NP];
__device__ __align__(16) fp16 g_Wc[KP1 * NP];
__device__ __align__(16) fp16 g_Wrs[KP1 * NP];
__device__ __align__(16) fp16 g_Wcs[KP1 * NP];
__device__ __align__(16) fp16 g_Wm[KPM * NP];

// ---------------- helpers ----------------------------------------------------
__device__ __forceinline__ uint32_t pack2(fp16 a, fp16 b) {
    fp162 t = __halves2half2(a, b);
    return *(uint32_t*)&t;
}
#define SWZ(x) ((x) ^ (((x) >> 3) & 0x70))
__device__ __forceinline__ void cp16(uint32_t dst, const void* src) {
    asm volatile("cp.async.cg.shared.global [%0], [%1], 16;" :: "r"(dst), "l"(src));
}
__device__ __forceinline__ void ldsm_x4(uint32_t& r0, uint32_t& r1, uint32_t& r2, uint32_t& r3,
                                        uint32_t addr) {
    asm volatile("ldmatrix.sync.aligned.m8n8.x4.shared.b16 {%0,%1,%2,%3}, [%4];"
                 : "=r"(r0), "=r"(r1), "=r"(r2), "=r"(r3) : "r"(addr));
}
__device__ __forceinline__ void ldsm_x4_t(uint32_t& r0, uint32_t& r1, uint32_t& r2, uint32_t& r3,
                                          uint32_t addr) {
    asm volatile("ldmatrix.sync.aligned.m8n8.x4.trans.shared.b16 {%0,%1,%2,%3}, [%4];"
                 : "=r"(r0), "=r"(r1), "=r"(r2), "=r"(r3) : "r"(addr));
}
__device__ __forceinline__ void mma_fp16(float* c, const uint32_t* a, const uint32_t* b) {
    asm volatile("mma.sync.aligned.m16n8k16.row.col.f32.f16.f16.f32 "
                 "{%0,%1,%2,%3}, {%4,%5,%6,%7}, {%8,%9}, {%0,%1,%2,%3};"
                 : "+f"(c[0]), "+f"(c[1]), "+f"(c[2]), "+f"(c[3])
                 : "r"(a[0]), "r"(a[1]), "r"(a[2]), "r"(a[3]), "r"(b[0]), "r"(b[1]));
}

// ---------------- graph preprocessing ----------------------------------------
__global__ void zero_ideg_kernel() {
    int i = blockIdx.x * blockDim.x + threadIdx.x;
    if (i < 4 * NN) g_ideg[i] = 0;
}

__global__ void degree_kernel(const int* __restrict__ er, const int* __restrict__ ec) {
    int i = blockIdx.x * blockDim.x + threadIdx.x;
    if (i < NE) {
        atomicAdd(&g_ideg[0 * NN + er[i]],      1);
        atomicAdd(&g_ideg[1 * NN + er[NE + i]], 1);
        atomicAdd(&g_ideg[2 * NN + ec[i]],      1);
        atomicAdd(&g_ideg[3 * NN + ec[NE + i]], 1);
    }
}

__global__ void norm_kernel() {
    int i = blockIdx.x * blockDim.x + threadIdx.x;
    if (i < 4 * NN) {
        int d = g_ideg[i];
        g_deg[i] = (d > 0) ? rsqrtf((float)d) : 0.f;
    }
}

// x fp32 -> fp16 table
__global__ void x_convert_kernel(const float2* __restrict__ x) {
    long i = (long)blockIdx.x * blockDim.x + threadIdx.x;
    if (i < (long)NN * DD / 2) {
        float2 v = x[i];
        *(uint32_t*)&g_xh[i * 2] = pack2(__float2half(v.x), __float2half(v.y));
    }
}

__global__ __launch_bounds__(SB) void scan1_kernel() {
    int gsel = blockIdx.y;
    const int* deg = g_ideg + (gsel ? 3 : 1) * NN;
    int i = blockIdx.x * SB + threadIdx.x;
    int v = (i < NN) ? deg[i] : 0;
    __shared__ int ws[32];
    #pragma unroll
    for (int o = 16; o > 0; o >>= 1) v += __shfl_xor_sync(0xFFFFFFFFu, v, o);
    if ((threadIdx.x & 31) == 0) ws[threadIdx.x >> 5] = v;
    __syncthreads();
    if (threadIdx.x < 32) {
        int s = (threadIdx.x < SB / 32) ? ws[threadIdx.x] : 0;
        #pragma unroll
        for (int o = 16; o > 0; o >>= 1) s += __shfl_xor_sync(0xFFFFFFFFu, s, o);
        if (threadIdx.x == 0) g_bsum[gsel][blockIdx.x] = s;
    }
}

__global__ __launch_bounds__(256) void scan2_kernel(int* __restrict__ off_r,
                                                    int* __restrict__ off_c) {
    __shared__ int ss[2][128];
    int t = threadIdx.x;
    int h = t >> 7;
    int j = t & 127;
    int v = (j < NSB) ? g_bsum[h][j] : 0;
    ss[h][j] = v;
    __syncthreads();
    #pragma unroll
    for (int d = 1; d < 128; d <<= 1) {
        int u = (j >= d) ? ss[h][j - d] : 0;
        __syncthreads();
        ss[h][j] += u;
        __syncthreads();
    }
    if (j < NSB) g_boff[h][j] = ss[h][j] - v;
    if (t == 0) { off_r[NN] = NE; off_c[NN] = NE; }
}

__global__ __launch_bounds__(SB) void scan3_kernel(int* __restrict__ off_r,
                                                   int* __restrict__ cur_r,
                                                   int* __restrict__ off_c,
                                                   int* __restrict__ cur_c) {
    int gsel = blockIdx.y;
    const int* deg = g_ideg + (gsel ? 3 : 1) * NN;
    int* off = gsel ? off_c : off_r;
    int* cur = gsel ? cur_c : cur_r;
    __shared__ int ss[SB];
    int i = blockIdx.x * SB + threadIdx.x;
    int v = (i < NN) ? deg[i] : 0;
    ss[threadIdx.x] = v;
    __syncthreads();
    #pragma unroll
    for (int d = 1; d < SB; d <<= 1) {
        int u = (threadIdx.x >= d) ? ss[threadIdx.x - d] : 0;
        __syncthreads();
        ss[threadIdx.x] += u;
        __syncthreads();
    }
    if (i < NN) {
        int excl = ss[threadIdx.x] - v + g_boff[gsel][blockIdx.x];
        off[i] = excl;
        cur[i] = excl;
    }
}

__global__ void fill_kernel(const int* __restrict__ edges,
                            int* __restrict__ cur, int* __restrict__ csr) {
    int i = blockIdx.x * blockDim.x + threadIdx.x;
    if (i < NE) {
        int s = edges[i];
        int d = edges[NE + i];
        int pos = atomicAdd(&cur[d], 1);
        csr[pos] = s;
    }
}

// one warp per node; fp16 x reads, fp32 accumulate, 2-edge unroll
__global__ __launch_bounds__(256) void gather_kernel(
    const int* __restrict__ csr, const int* __restrict__ off,
    const float* __restrict__ nsrc, const float* __restrict__ ndst,
    fp16* __restrict__ Ah) {
    int warp = (int)((blockIdx.x * (long)blockDim.x + threadIdx.x) >> 5);
    int lane = threadIdx.x & 31;
    if (warp >= NN) return;
    int o0 = off[warp], o1 = off[warp + 1];
    float4 a0 = make_float4(0.f, 0.f, 0.f, 0.f);
    float4 a1 = a0, a2 = a0;
    auto accum = [&](int s, float ns) {
        const uint2* xr = (const uint2*)(g_xh + (size_t)s * DD);
        uint2 u = xr[lane];
        float2 p0 = __half22float2(*(fp162*)&u.x);
        float2 p1 = __half22float2(*(fp162*)&u.y);
        a0.x += p0.x * ns; a0.y += p0.y * ns; a0.z += p1.x * ns; a0.w += p1.y * ns;
        u = xr[32 + lane];
        p0 = __half22float2(*(fp162*)&u.x);
        p1 = __half22float2(*(fp162*)&u.y);
        a1.x += p0.x * ns; a1.y += p0.y * ns; a1.z += p1.x * ns; a1.w += p1.y * ns;
        if (lane < 11) {
            u = xr[64 + lane];
            p0 = __half22float2(*(fp162*)&u.x);
            p1 = __half22float2(*(fp162*)&u.y);
            a2.x += p0.x * ns; a2.y += p0.y * ns; a2.z += p1.x * ns; a2.w += p1.y * ns;
        }
    };
    int j = o0;
    for (; j + 1 < o1; j += 2) {
        int s0 = csr[j], s1 = csr[j + 1];
        float ns0 = nsrc[s0], ns1 = nsrc[s1];
        accum(s0, ns0);
        accum(s1, ns1);
    }
    if (j < o1) {
        int s0 = csr[j];
        accum(s0, nsrc[s0]);
    }
    float nd = ndst[warp];
    size_t orow = (size_t)warp * KP1;
    auto store4 = [&](float4 a, int f4i) {
        uint2 hh = make_uint2(
            pack2(__float2half(a.x * nd), __float2half(a.y * nd)),
            pack2(__float2half(a.z * nd), __float2half(a.w * nd)));
        *(uint2*)&Ah[orow + f4i * 4] = hh;
    };
    store4(a0, lane);
    store4(a1, 32 + lane);
    if (lane < 11) store4(a2, 64 + lane);
    if (lane < 20) Ah[orow + 300 + lane] = __float2half(0.f);
}

// zero tail rows [NN, MP) of agg + mrg planes
__global__ void tail_zero_kernel() {
    int i = blockIdx.x * blockDim.x + threadIdx.x;
    const int nAgg = (MP - NN) * KP1;
    const int nMrg = (MP - NN) * KPM;
    fp16 z = __float2half(0.f);
    if (i < nAgg) {
        size_t o = (size_t)NN * KP1 + i;
        g_aggr[o] = z;
        g_aggc[o] = z;
    }
    if (i < nMrg) g_mrg[(size_t)NN * KPM + i] = z;
}

// weight (K x Ncols fp32) -> fp16 plane (KPp x NP), zero padded
__global__ void w_convert_kernel(const float* __restrict__ W, int K, int Ncols, int KPp,
                                 fp16* __restrict__ Wh) {
    int idx = blockIdx.x * blockDim.x + threadIdx.x;
    if (idx >= KPp * NP) return;
    int k = idx / NP;
    int n = idx - k * NP;
    float v = (k < K && n < Ncols) ? W[(size_t)k * Ncols + n] : 0.f;
    Wh[idx] = __float2half(v);
}

// ====== Tensor-core GEMM: fp16 single-pass, SW128, GBK=64, 2-stage ==========
// Dual-problem launch: blockIdx.z in {0,1} selects operand set (A2/B2/bias2/C2).
// mode 0: fp32 out (guarded). mode 1: fp16 plane, zero-fill full padded tile.
// mode 2: fp16 out, store ONLY valid elements (for aliased mrg halves).
#define GBM 128
#define GBN 64
#define GBK 64
#define A_PL 16384u
#define B_PL 8192u
#define STG (A_PL + B_PL)           // 24576
#define SMEM_GEMM (2 * STG)         // 49152

__global__ __launch_bounds__(256) void gemm_tc2_kernel(
    const fp16* __restrict__ A1p, const fp16* __restrict__ A2p, int lda,
    const fp16* __restrict__ B1p, const fp16* __restrict__ B2p,
    const float* __restrict__ bias1, const float* __restrict__ bias2,
    int M, int Ncols, int nK, int mode, int relu,
    float* __restrict__ Cf, int ldc,
    fp16* __restrict__ C1h, fp16* __restrict__ C2h, int ldcp)
{
    extern __shared__ __align__(128) char smem[];
    const uint32_t sb = (uint32_t)__cvta_generic_to_shared(smem);

    const fp16* Ap = (blockIdx.z == 0) ? A1p : A2p;
    const fp16* Bp = (blockIdx.z == 0) ? B1p : B2p;
    const float* bias = (blockIdx.z == 0) ? bias1 : bias2;
    fp16* Ch = (blockIdx.z == 0) ? C1h : C2h;

    const int t = threadIdx.x;
    const int wid = t >> 5;
    const int lane = t & 31;
    const int warp_m = wid >> 1;
    const int warp_n = wid & 1;
    const int m0 = blockIdx.y * GBM;
    const int n0 = blockIdx.x * GBN;

    float acc[2][4][4];
    #pragma unroll
    for (int mi = 0; mi < 2; mi++)
        #pragma unroll
        for (int ni = 0; ni < 4; ni++)
            #pragma unroll
            for (int j = 0; j < 4; j++) acc[mi][ni][j] = 0.f;

    auto load_stage = [&](int stage, int k0) {
        const uint32_t base = sb + (uint32_t)stage * STG;
        const uint32_t aA = base;
        const uint32_t aB = base + A_PL;
        #pragma unroll
        for (int i = 0; i < 4; i++) {
            int idx = i * 256 + t;
            int r = idx >> 3, c = idx & 7;
            uint32_t d = SWZ((uint32_t)(r * 128 + c * 16));
            cp16(aA + d, Ap + (size_t)(m0 + r) * lda + k0 + c * 8);
        }
        #pragma unroll
        for (int i = 0; i < 2; i++) {
            int idx = i * 256 + t;
            int r = idx >> 3, c = idx & 7;
            uint32_t d = SWZ((uint32_t)(r * 128 + c * 16));
            cp16(aB + d, Bp + (size_t)(k0 + r) * NP + n0 + c * 8);
        }
        asm volatile("cp.async.commit_group;");
    };

    load_stage(0, 0);

    const int lrow = lane & 15;
    const int lhi = lane >> 4;

    for (int kt = 0; kt < nK; kt++) {
        if (kt + 1 < nK) {
            load_stage((kt + 1) & 1, (kt + 1) * GBK);
            asm volatile("cp.async.wait_group 1;");
        } else {
            asm volatile("cp.async.wait_group 0;");
        }
        __syncthreads();

        const uint32_t base = sb + (uint32_t)(kt & 1) * STG;
        const uint32_t aA = base;
        const uint32_t aB = base + A_PL;

        #pragma unroll
        for (int ks = 0; ks < 4; ks++) {
            uint32_t ah[2][4];
            #pragma unroll
            for (int mi = 0; mi < 2; mi++) {
                int row = warp_m * 32 + mi * 16 + lrow;
                uint32_t off = SWZ((uint32_t)(row * 128 + ks * 32 + lhi * 16));
                ldsm_x4(ah[mi][0], ah[mi][1], ah[mi][2], ah[mi][3], aA + off);
            }
            uint32_t bh[4][2];
            #pragma unroll
            for (int nj = 0; nj < 2; nj++) {
                int krow = ks * 16 + lrow;
                uint32_t off = SWZ((uint32_t)(krow * 128 + warp_n * 64 + nj * 32 + lhi * 16));
                uint32_t r0, r1, r2, r3;
                ldsm_x4_t(r0, r1, r2, r3, aB + off);
                bh[nj * 2 + 0][0] = r0; bh[nj * 2 + 0][1] = r1;
                bh[nj * 2 + 1][0] = r2; bh[nj * 2 + 1][1] = r3;
            }
            #pragma unroll
            for (int mi = 0; mi < 2; mi++)
                #pragma unroll
                for (int ni = 0; ni < 4; ni++)
                    mma_fp16(acc[mi][ni], ah[mi], bh[ni]);
        }
        __syncthreads();
    }

    // ---- epilogue ----
    const int g = lane >> 2;
    const int tig = lane & 3;
    #pragma unroll
    for (int mi = 0; mi < 2; mi++) {
        #pragma unroll
        for (int ni = 0; ni < 4; ni++) {
            int col = n0 + warp_n * 32 + ni * 8 + tig * 2;
            float bx = 0.f, by = 0.f;
            if (bias != nullptr && col < Ncols) {
                bx = bias[col];
                if (col + 1 < Ncols) by = bias[col + 1];
            }
            #pragma unroll
            for (int rr = 0; rr < 2; rr++) {
                int row = m0 + warp_m * 32 + mi * 16 + g + rr * 8;
                float vx = acc[mi][ni][rr * 2 + 0] + bx;
                float vy = acc[mi][ni][rr * 2 + 1] + by;
                if (relu) { vx = fmaxf(vx, 0.f); vy = fmaxf(vy, 0.f); }
                bool ok = (row < M) && (col < Ncols);
                if (mode == 0) {
                    if (ok)
                        *(float2*)(Cf + (size_t)row * ldc + col) = make_float2(vx, vy);
                } else if (mode == 1) {
                    if (!ok) { vx = 0.f; vy = 0.f; }
                    *(uint32_t*)&Ch[(size_t)row * ldcp + col] =
                        pack2(__float2half(vx), __float2half(vy));
                } else {
                    if (ok)
                        *(uint32_t*)&Ch[(size_t)row * ldcp + col] =
                            pack2(__float2half(vx), __float2half(vy));
                }
            }
        }
    }
}

// ---------------- LayerNorm (fp32, in place) --------------------------------
__global__ void ln_kernel(float* __restrict__ X, int ld,
                          const float* __restrict__ gamma,
                          const float* __restrict__ beta, int M) {
    int warp = (int)((blockIdx.x * (long)blockDim.x + threadIdx.x) >> 5);
    int lane = threadIdx.x & 31;
    if (warp >= M) return;
    float* p = X + (size_t)warp * ld;
    float v[10];
    float sum = 0.f;
    #pragma unroll
    for (int k = 0; k < 10; k++) {
        int c = lane + 32 * k;
        v[k] = (c < DD) ? p[c] : 0.f;
        sum += v[k];
    }
    #pragma unroll
    for (int o = 16; o > 0; o >>= 1) sum += __shfl_xor_sync(0xFFFFFFFFu, sum, o);
    float mu = sum * (1.f / DD);
    float var = 0.f;
    #pragma unroll
    for (int k = 0; k < 10; k++) {
        int c = lane + 32 * k;
        float d = (c < DD) ? (v[k] - mu) : 0.f;
        var += d * d;
    }
    #pragma unroll
    for (int o = 16; o > 0; o >>= 1) var += __shfl_xor_sync(0xFFFFFFFFu, var, o);
    float rsig = rsqrtf(var * (1.f / DD) + 1e-5f);
    #pragma unroll
    for (int k = 0; k < 10; k++) {
        int c = lane + 32 * k;
        if (c < DD) p[c] = (v[k] - mu) * rsig * gamma[c] + beta[c];
    }
}

// in-place LN on the two fp16 halves of each mrg row; zero pad cols [600,640)
__global__ void ln_mrg_kernel(const float* __restrict__ g0, const float* __restrict__ b0,
                              const float* __restrict__ g1, const float* __restrict__ b1) {
    int warp = (int)((blockIdx.x * (long)blockDim.x + threadIdx.x) >> 5);
    int lane = threadIdx.x & 31;
    if (warp >= NN) return;
    size_t orow = (size_t)warp * KPM;
    #pragma unroll
    for (int half = 0; half < 2; half++) {
        fp16* p = g_mrg + orow + half * DD;
        const float* gamma = half ? g1 : g0;
        const float* beta  = half ? b1 : b0;
        float v[10];
        float sum = 0.f;
        #pragma unroll
        for (int k = 0; k < 10; k++) {
            int c = lane + 32 * k;
            v[k] = (c < DD) ? __half2float(p[c]) : 0.f;
            sum += v[k];
        }
        #pragma unroll
        for (int o = 16; o > 0; o >>= 1) sum += __shfl_xor_sync(0xFFFFFFFFu, sum, o);
        float mu = sum * (1.f / DD);
        float var = 0.f;
        #pragma unroll
        for (int k = 0; k < 10; k++) {
            int c = lane + 32 * k;
            float d = (c < DD) ? (v[k] - mu) : 0.f;
            var += d * d;
        }
        #pragma unroll
        for (int o = 16; o > 0; o >>= 1) var += __shfl_xor_sync(0xFFFFFFFFu, var, o);
        float rsig = rsqrtf(var * (1.f / DD) + 1e-5f);
        #pragma unroll
        for (int k = 0; k < 10; k++) {
            int c = lane + 32 * k;
            if (c < DD)
                p[c] = __float2half((v[k] - mu) * rsig * gamma[c] + beta[c]);
        }
    }
    fp16 z = __float2half(0.f);
    g_mrg[orow + 600 + lane] = z;
    if (lane < 8) g_mrg[orow + 632 + lane] = z;
}

// ---------------- launch ----------------------------------------------------
extern "C" void kernel_launch(void* const* d_in, const int* in_sizes, int n_in,
                              void* d_out, int out_size) {
    const float* x    = (const float*)d_in[0];
    const int*   er   = (const int*)d_in[1];
    const int*   ec   = (const int*)d_in[2];
    const float* Wr   = (const float*)d_in[3];
    const float* br   = (const float*)d_in[4];
    const float* Wc   = (const float*)d_in[5];
    const float* bc   = (const float*)d_in[6];
    const float* Wrs  = (const float*)d_in[7];
    const float* brs  = (const float*)d_in[8];
    const float* g_rs = (const float*)d_in[9];
    const float* b_rs = (const float*)d_in[10];
    const float* Wcs  = (const float*)d_in[11];
    const float* bcs  = (const float*)d_in[12];
    const float* g_cs = (const float*)d_in[13];
    const float* b_cs = (const float*)d_in[14];
    const float* Wm   = (const float*)d_in[15];
    const float* bm   = (const float*)d_in[16];
    const float* g_m  = (const float*)d_in[17];
    const float* b_m  = (const float*)d_in[18];
    float* out = (float*)d_out;

    float* deg;
    cudaGetSymbolAddress((void**)&deg, g_deg);
    int *off_r, *off_c, *cur_r, *cur_c, *csr_r, *csr_c;
    cudaGetSymbolAddress((void**)&off_r, g_off_r);
    cudaGetSymbolAddress((void**)&off_c, g_off_c);
    cudaGetSymbolAddress((void**)&cur_r, g_cur_r);
    cudaGetSymbolAddress((void**)&cur_c, g_cur_c);
    cudaGetSymbolAddress((void**)&csr_r, g_csr_r);
    cudaGetSymbolAddress((void**)&csr_c, g_csr_c);

    fp16 *aggr, *aggc, *rowg, *colg, *mrg;
    fp16 *pWr, *pWc, *pWrs, *pWcs, *pWm;
    cudaGetSymbolAddress((void**)&aggr, g_aggr);
    cudaGetSymbolAddress((void**)&aggc, g_aggc);
    cudaGetSymbolAddress((void**)&rowg, g_rowg);
    cudaGetSymbolAddress((void**)&colg, g_colg);
    cudaGetSymbolAddress((void**)&mrg,  g_mrg);
    cudaGetSymbolAddress((void**)&pWr,  g_Wr);
    cudaGetSymbolAddress((void**)&pWc,  g_Wc);
    cudaGetSymbolAddress((void**)&pWrs, g_Wrs);
    cudaGetSymbolAddress((void**)&pWcs, g_Wcs);
    cudaGetSymbolAddress((void**)&pWm,  g_Wm);

    cudaFuncSetAttribute(gemm_tc2_kernel,
                         cudaFuncAttributeMaxDynamicSharedMemorySize, SMEM_GEMM);

    // graph preprocessing + x conversion
    zero_ideg_kernel<<<(4 * NN + 255) / 256, 256>>>();
    degree_kernel<<<(NE + 255) / 256, 256>>>(er, ec);
    x_convert_kernel<<<(int)(((long)NN * DD / 2 + 255) / 256), 256>>>((const float2*)x);
    norm_kernel<<<(4 * NN + 255) / 256, 256>>>();
    dim3 sgrid(NSB, 2);
    scan1_kernel<<<sgrid, SB>>>();
    scan2_kernel<<<1, 256>>>(off_r, off_c);
    scan3_kernel<<<sgrid, SB>>>(off_r, cur_r, off_c, cur_c);
    fill_kernel<<<(NE + 255) / 256, 256>>>(er, cur_r, csr_r);
    fill_kernel<<<(NE + 255) / 256, 256>>>(ec, cur_c, csr_c);
    int ggrid = (NN * 32 + 255) / 256;
    gather_kernel<<<ggrid, 256>>>(csr_r, off_r, deg + 0 * NN, deg + 1 * NN, aggr);
    gather_kernel<<<ggrid, 256>>>(csr_c, off_c, deg + 2 * NN, deg + 3 * NN, aggc);
    tail_zero_kernel<<<((MP - NN) * KPM + 255) / 256, 256>>>();

    // weight converts
    int wgrid = (KP1 * NP + 255) / 256;
    w_convert_kernel<<<wgrid, 256>>>(Wr,  DD, DD, KP1, pWr);
    w_convert_kernel<<<wgrid, 256>>>(Wc,  DD, DD, KP1, pWc);
    w_convert_kernel<<<wgrid, 256>>>(Wrs, DD, DD, KP1, pWrs);
    w_convert_kernel<<<wgrid, 256>>>(Wcs, DD, DD, KP1, pWcs);
    w_convert_kernel<<<(KPM * NP + 255) / 256, 256>>>(Wm, 2 * DD, DD, KPM, pWm);

    dim3 gg2(NP / GBN, MP / GBM, 2);   // (5, 782, 2) fused pair
    dim3 gg1(NP / GBN, MP / GBM, 1);
    const int nK1 = KP1 / GBK;     // 5
    const int nKm = KPM / GBK;     // 10

    // fused GraphConv GEMMs: relu -> fp16 planes (zero-filled padding)
    gemm_tc2_kernel<<<gg2, 256, SMEM_GEMM>>>(aggr, aggc, KP1, pWr, pWc, br, bc,
        NN, DD, nK1, 1, 1, nullptr, 0, rowg, colg, KP1);

    // fused support GEMMs -> fp16 mrg halves (mode 2: valid-only stores)
    gemm_tc2_kernel<<<gg2, 256, SMEM_GEMM>>>(rowg, colg, KP1, pWrs, pWcs, brs, bcs,
        NN, DD, nK1, 2, 0, nullptr, 0, mrg, mrg + DD, KPM);

    // in-place fp16 LN on both halves (+ zero pad cols)
    int lngrid = (NN + 7) / 8;
    ln_mrg_kernel<<<lngrid, 256>>>(g_rs, b_rs, g_cs, b_cs);

    // merge GEMM (K=640) -> fp32 out, then final LN
    gemm_tc2_kernel<<<gg1, 256, SMEM_GEMM>>>(mrg, mrg, KPM, pWm, pWm, bm, bm,
        NN, DD, nKm, 0, 0, out, DD, nullptr, nullptr, 0);
    ln_kernel<<<lngrid, 256>>>(out, DD, g_m, b_m, NN);
}

// round 14
// speedup vs baseline: 1.0521x; 1.0167x over previous
#include <cuda_runtime.h>
#include <cuda_fp16.h>
#include <cstddef>
#include <cstdint>

#define NN 100000
#define NE 1000000
#define DD 300
#define MP 100096      // NN padded to 128
#define KP1 320        // K=300 padded
#define NP  320        // N=300 padded
#define KPM 640        // merge K=600 padded

typedef __half fp16;
typedef __half2 fp162;

// ---------------- scratch (device globals; no allocation allowed) ----------
__device__ int   g_ideg[4 * NN];
__device__ float g_deg[4 * NN];
__device__ int   g_off_r[NN + 1], g_off_c[NN + 1];
__device__ int   g_cur_r[NN],     g_cur_c[NN];
__device__ int   g_csr_r[NE],     g_csr_c[NE];

#define SB 1024
#define NSB ((NN + SB - 1) / SB)   // 98
__device__ int g_bsum[2][NSB];
__device__ int g_boff[2][NSB];

// fp16 feature table (NN x DD)
__device__ __align__(16) fp16 g_xh[(size_t)NN * DD];
// fp16 operand planes (padded, M x K row-major)
__device__ __align__(16) fp16 g_aggr[(size_t)MP * KP1];
__device__ __align__(16) fp16 g_aggc[(size_t)MP * KP1];
__device__ __align__(16) fp16 g_rowg[(size_t)MP * KP1];
__device__ __align__(16) fp16 g_colg[(size_t)MP * KP1];
__device__ __align__(16) fp16 g_mrg[(size_t)MP * KPM];
// weight planes (single fp16): K x N row-major
__device__ __align__(16) fp16 g_Wr[KP1 * NP];
__device__ __align__(16) fp16 g_Wc[KP1 * NP];
__device__ __align__(16) fp16 g_Wrs[KP1 * NP];
__device__ __align__(16) fp16 g_Wcs[KP1 * NP];
__device__ __align__(16) fp16 g_Wm[KPM * NP];

// ---------------- helpers ----------------------------------------------------
__device__ __forceinline__ uint32_t pack2(fp16 a, fp16 b) {
    fp162 t = __halves2half2(a, b);
    return *(uint32_t*)&t;
}
#define SWZ(x) ((x) ^ (((x) >> 3) & 0x70))
__device__ __forceinline__ void cp16(uint32_t dst, const void* src) {
    asm volatile("cp.async.cg.shared.global [%0], [%1], 16;" :: "r"(dst), "l"(src));
}
__device__ __forceinline__ void ldsm_x4(uint32_t& r0, uint32_t& r1, uint32_t& r2, uint32_t& r3,
                                        uint32_t addr) {
    asm volatile("ldmatrix.sync.aligned.m8n8.x4.shared.b16 {%0,%1,%2,%3}, [%4];"
                 : "=r"(r0), "=r"(r1), "=r"(r2), "=r"(r3) : "r"(addr));
}
__device__ __forceinline__ void ldsm_x4_t(uint32_t& r0, uint32_t& r1, uint32_t& r2, uint32_t& r3,
                                          uint32_t addr) {
    asm volatile("ldmatrix.sync.aligned.m8n8.x4.trans.shared.b16 {%0,%1,%2,%3}, [%4];"
                 : "=r"(r0), "=r"(r1), "=r"(r2), "=r"(r3) : "r"(addr));
}
__device__ __forceinline__ void mma_fp16(float* c, const uint32_t* a, const uint32_t* b) {
    asm volatile("mma.sync.aligned.m16n8k16.row.col.f32.f16.f16.f32 "
                 "{%0,%1,%2,%3}, {%4,%5,%6,%7}, {%8,%9}, {%0,%1,%2,%3};"
                 : "+f"(c[0]), "+f"(c[1]), "+f"(c[2]), "+f"(c[3])
                 : "r"(a[0]), "r"(a[1]), "r"(a[2]), "r"(a[3]), "r"(b[0]), "r"(b[1]));
}

// ---------------- graph preprocessing ----------------------------------------
__global__ void zero_ideg_kernel() {
    int i = blockIdx.x * blockDim.x + threadIdx.x;
    if (i < 4 * NN) g_ideg[i] = 0;
}

__global__ void degree_kernel(const int* __restrict__ er, const int* __restrict__ ec) {
    int i = blockIdx.x * blockDim.x + threadIdx.x;
    if (i < NE) {
        atomicAdd(&g_ideg[0 * NN + er[i]],      1);
        atomicAdd(&g_ideg[1 * NN + er[NE + i]], 1);
        atomicAdd(&g_ideg[2 * NN + ec[i]],      1);
        atomicAdd(&g_ideg[3 * NN + ec[NE + i]], 1);
    }
}

__global__ void norm_kernel() {
    int i = blockIdx.x * blockDim.x + threadIdx.x;
    if (i < 4 * NN) {
        int d = g_ideg[i];
        g_deg[i] = (d > 0) ? rsqrtf((float)d) : 0.f;
    }
}

// x fp32 -> fp16 table
__global__ void x_convert_kernel(const float2* __restrict__ x) {
    long i = (long)blockIdx.x * blockDim.x + threadIdx.x;
    if (i < (long)NN * DD / 2) {
        float2 v = x[i];
        *(uint32_t*)&g_xh[i * 2] = pack2(__float2half(v.x), __float2half(v.y));
    }
}

__global__ __launch_bounds__(SB) void scan1_kernel() {
    int gsel = blockIdx.y;
    const int* deg = g_ideg + (gsel ? 3 : 1) * NN;
    int i = blockIdx.x * SB + threadIdx.x;
    int v = (i < NN) ? deg[i] : 0;
    __shared__ int ws[32];
    #pragma unroll
    for (int o = 16; o > 0; o >>= 1) v += __shfl_xor_sync(0xFFFFFFFFu, v, o);
    if ((threadIdx.x & 31) == 0) ws[threadIdx.x >> 5] = v;
    __syncthreads();
    if (threadIdx.x < 32) {
        int s = (threadIdx.x < SB / 32) ? ws[threadIdx.x] : 0;
        #pragma unroll
        for (int o = 16; o > 0; o >>= 1) s += __shfl_xor_sync(0xFFFFFFFFu, s, o);
        if (threadIdx.x == 0) g_bsum[gsel][blockIdx.x] = s;
    }
}

__global__ __launch_bounds__(256) void scan2_kernel(int* __restrict__ off_r,
                                                    int* __restrict__ off_c) {
    __shared__ int ss[2][128];
    int t = threadIdx.x;
    int h = t >> 7;
    int j = t & 127;
    int v = (j < NSB) ? g_bsum[h][j] : 0;
    ss[h][j] = v;
    __syncthreads();
    #pragma unroll
    for (int d = 1; d < 128; d <<= 1) {
        int u = (j >= d) ? ss[h][j - d] : 0;
        __syncthreads();
        ss[h][j] += u;
        __syncthreads();
    }
    if (j < NSB) g_boff[h][j] = ss[h][j] - v;
    if (t == 0) { off_r[NN] = NE; off_c[NN] = NE; }
}

__global__ __launch_bounds__(SB) void scan3_kernel(int* __restrict__ off_r,
                                                   int* __restrict__ cur_r,
                                                   int* __restrict__ off_c,
                                                   int* __restrict__ cur_c) {
    int gsel = blockIdx.y;
    const int* deg = g_ideg + (gsel ? 3 : 1) * NN;
    int* off = gsel ? off_c : off_r;
    int* cur = gsel ? cur_c : cur_r;
    __shared__ int ss[SB];
    int i = blockIdx.x * SB + threadIdx.x;
    int v = (i < NN) ? deg[i] : 0;
    ss[threadIdx.x] = v;
    __syncthreads();
    #pragma unroll
    for (int d = 1; d < SB; d <<= 1) {
        int u = (threadIdx.x >= d) ? ss[threadIdx.x - d] : 0;
        __syncthreads();
        ss[threadIdx.x] += u;
        __syncthreads();
    }
    if (i < NN) {
        int excl = ss[threadIdx.x] - v + g_boff[gsel][blockIdx.x];
        off[i] = excl;
        cur[i] = excl;
    }
}

__global__ void fill_kernel(const int* __restrict__ edges,
                            int* __restrict__ cur, int* __restrict__ csr) {
    int i = blockIdx.x * blockDim.x + threadIdx.x;
    if (i < NE) {
        int s = edges[i];
        int d = edges[NE + i];
        int pos = atomicAdd(&cur[d], 1);
        csr[pos] = s;
    }
}

// one warp per node; fp16 x reads, fp32 accumulate
__global__ __launch_bounds__(256) void gather_kernel(
    const int* __restrict__ csr, const int* __restrict__ off,
    const float* __restrict__ nsrc, const float* __restrict__ ndst,
    fp16* __restrict__ Ah) {
    int warp = (int)((blockIdx.x * (long)blockDim.x + threadIdx.x) >> 5);
    int lane = threadIdx.x & 31;
    if (warp >= NN) return;
    int o0 = off[warp], o1 = off[warp + 1];
    float4 a0 = make_float4(0.f, 0.f, 0.f, 0.f);
    float4 a1 = a0, a2 = a0;
    for (int j = o0; j < o1; j++) {
        int s = csr[j];
        float ns = nsrc[s];
        const uint2* xr = (const uint2*)(g_xh + (size_t)s * DD);
        uint2 u = xr[lane];
        float2 p0 = __half22float2(*(fp162*)&u.x);
        float2 p1 = __half22float2(*(fp162*)&u.y);
        a0.x += p0.x * ns; a0.y += p0.y * ns; a0.z += p1.x * ns; a0.w += p1.y * ns;
        u = xr[32 + lane];
        p0 = __half22float2(*(fp162*)&u.x);
        p1 = __half22float2(*(fp162*)&u.y);
        a1.x += p0.x * ns; a1.y += p0.y * ns; a1.z += p1.x * ns; a1.w += p1.y * ns;
        if (lane < 11) {
            u = xr[64 + lane];
            p0 = __half22float2(*(fp162*)&u.x);
            p1 = __half22float2(*(fp162*)&u.y);
            a2.x += p0.x * ns; a2.y += p0.y * ns; a2.z += p1.x * ns; a2.w += p1.y * ns;
        }
    }
    float nd = ndst[warp];
    size_t orow = (size_t)warp * KP1;
    auto store4 = [&](float4 a, int f4i) {
        uint2 hh = make_uint2(
            pack2(__float2half(a.x * nd), __float2half(a.y * nd)),
            pack2(__float2half(a.z * nd), __float2half(a.w * nd)));
        *(uint2*)&Ah[orow + f4i * 4] = hh;
    };
    store4(a0, lane);
    store4(a1, 32 + lane);
    if (lane < 11) store4(a2, 64 + lane);
    if (lane < 20) Ah[orow + 300 + lane] = __float2half(0.f);
}

// zero tail rows [NN, MP) of agg + mrg planes
__global__ void tail_zero_kernel() {
    int i = blockIdx.x * blockDim.x + threadIdx.x;
    const int nAgg = (MP - NN) * KP1;
    const int nMrg = (MP - NN) * KPM;
    fp16 z = __float2half(0.f);
    if (i < nAgg) {
        size_t o = (size_t)NN * KP1 + i;
        g_aggr[o] = z;
        g_aggc[o] = z;
    }
    if (i < nMrg) g_mrg[(size_t)NN * KPM + i] = z;
}

// weight (K x Ncols fp32) -> fp16 plane (KPp x NP), zero padded
__global__ void w_convert_kernel(const float* __restrict__ W, int K, int Ncols, int KPp,
                                 fp16* __restrict__ Wh) {
    int idx = blockIdx.x * blockDim.x + threadIdx.x;
    if (idx >= KPp * NP) return;
    int k = idx / NP;
    int n = idx - k * NP;
    float v = (k < K && n < Ncols) ? W[(size_t)k * Ncols + n] : 0.f;
    Wh[idx] = __float2half(v);
}

// ====== Tensor-core GEMM: fp16 single-pass, SW128, GBK=64, 3-stage ==========
// mode 0: fp32 out (guarded). mode 1: fp16 plane, zero-fill full padded tile.
// mode 2: fp16 out, store ONLY valid elements (for aliased mrg halves).
#define GBM 128
#define GBN 64
#define GBK 64
#define A_PL 16384u
#define B_PL 8192u
#define STG (A_PL + B_PL)           // 24576
#define NSTAGE 3
#define SMEM_GEMM (NSTAGE * STG)    // 73728

__global__ __launch_bounds__(256) void gemm_tc2_kernel(
    const fp16* __restrict__ Ap, int lda,
    const fp16* __restrict__ Bp,
    const float* __restrict__ bias,
    int M, int Ncols, int nK, int mode, int relu,
    float* __restrict__ Cf, int ldc,
    fp16* __restrict__ Ch, int ldcp)
{
    extern __shared__ __align__(128) char smem[];
    const uint32_t sb = (uint32_t)__cvta_generic_to_shared(smem);

    const int t = threadIdx.x;
    const int wid = t >> 5;
    const int lane = t & 31;
    const int warp_m = wid >> 1;
    const int warp_n = wid & 1;
    const int m0 = blockIdx.y * GBM;
    const int n0 = blockIdx.x * GBN;

    float acc[2][4][4];
    #pragma unroll
    for (int mi = 0; mi < 2; mi++)
        #pragma unroll
        for (int ni = 0; ni < 4; ni++)
            #pragma unroll
            for (int j = 0; j < 4; j++) acc[mi][ni][j] = 0.f;

    auto load_stage = [&](int stage, int k0) {
        const uint32_t base = sb + (uint32_t)stage * STG;
        const uint32_t aA = base;
        const uint32_t aB = base + A_PL;
        #pragma unroll
        for (int i = 0; i < 4; i++) {
            int idx = i * 256 + t;
            int r = idx >> 3, c = idx & 7;
            uint32_t d = SWZ((uint32_t)(r * 128 + c * 16));
            cp16(aA + d, Ap + (size_t)(m0 + r) * lda + k0 + c * 8);
        }
        #pragma unroll
        for (int i = 0; i < 2; i++) {
            int idx = i * 256 + t;
            int r = idx >> 3, c = idx & 7;
            uint32_t d = SWZ((uint32_t)(r * 128 + c * 16));
            cp16(aB + d, Bp + (size_t)(k0 + r) * NP + n0 + c * 8);
        }
        asm volatile("cp.async.commit_group;");
    };

    // prologue: two stages in flight
    load_stage(0, 0);
    if (nK > 1) load_stage(1, GBK);

    const int lrow = lane & 15;
    const int lhi = lane >> 4;

    int stage = 0;
    for (int kt = 0; kt < nK; kt++) {
        if (kt + 2 < nK) {
            int s2 = stage + 2; if (s2 >= NSTAGE) s2 -= NSTAGE;
            load_stage(s2, (kt + 2) * GBK);
            asm volatile("cp.async.wait_group 2;");
        } else if (kt + 1 < nK) {
            asm volatile("cp.async.wait_group 1;");
        } else {
            asm volatile("cp.async.wait_group 0;");
        }
        __syncthreads();

        const uint32_t base = sb + (uint32_t)stage * STG;
        const uint32_t aA = base;
        const uint32_t aB = base + A_PL;

        #pragma unroll
        for (int ks = 0; ks < 4; ks++) {
            uint32_t ah[2][4];
            #pragma unroll
            for (int mi = 0; mi < 2; mi++) {
                int row = warp_m * 32 + mi * 16 + lrow;
                uint32_t off = SWZ((uint32_t)(row * 128 + ks * 32 + lhi * 16));
                ldsm_x4(ah[mi][0], ah[mi][1], ah[mi][2], ah[mi][3], aA + off);
            }
            uint32_t bh[4][2];
            #pragma unroll
            for (int nj = 0; nj < 2; nj++) {
                int krow = ks * 16 + lrow;
                uint32_t off = SWZ((uint32_t)(krow * 128 + warp_n * 64 + nj * 32 + lhi * 16));
                uint32_t r0, r1, r2, r3;
                ldsm_x4_t(r0, r1, r2, r3, aB + off);
                bh[nj * 2 + 0][0] = r0; bh[nj * 2 + 0][1] = r1;
                bh[nj * 2 + 1][0] = r2; bh[nj * 2 + 1][1] = r3;
            }
            #pragma unroll
            for (int mi = 0; mi < 2; mi++)
                #pragma unroll
                for (int ni = 0; ni < 4; ni++)
                    mma_fp16(acc[mi][ni], ah[mi], bh[ni]);
        }
        __syncthreads();
        stage++; if (stage >= NSTAGE) stage = 0;
    }

    // ---- epilogue ----
    const int g = lane >> 2;
    const int tig = lane & 3;
    #pragma unroll
    for (int mi = 0; mi < 2; mi++) {
        #pragma unroll
        for (int ni = 0; ni < 4; ni++) {
            int col = n0 + warp_n * 32 + ni * 8 + tig * 2;
            float bx = 0.f, by = 0.f;
            if (bias != nullptr && col < Ncols) {
                bx = bias[col];
                if (col + 1 < Ncols) by = bias[col + 1];
            }
            #pragma unroll
            for (int rr = 0; rr < 2; rr++) {
                int row = m0 + warp_m * 32 + mi * 16 + g + rr * 8;
                float vx = acc[mi][ni][rr * 2 + 0] + bx;
                float vy = acc[mi][ni][rr * 2 + 1] + by;
                if (relu) { vx = fmaxf(vx, 0.f); vy = fmaxf(vy, 0.f); }
                bool ok = (row < M) && (col < Ncols);
                if (mode == 0) {
                    if (ok)
                        *(float2*)(Cf + (size_t)row * ldc + col) = make_float2(vx, vy);
                } else if (mode == 1) {
                    if (!ok) { vx = 0.f; vy = 0.f; }
                    *(uint32_t*)&Ch[(size_t)row * ldcp + col] =
                        pack2(__float2half(vx), __float2half(vy));
                } else {
                    if (ok)
                        *(uint32_t*)&Ch[(size_t)row * ldcp + col] =
                            pack2(__float2half(vx), __float2half(vy));
                }
            }
        }
    }
}

// ---------------- LayerNorm (fp32, in place) --------------------------------
__global__ void ln_kernel(float* __restrict__ X, int ld,
                          const float* __restrict__ gamma,
                          const float* __restrict__ beta, int M) {
    int warp = (int)((blockIdx.x * (long)blockDim.x + threadIdx.x) >> 5);
    int lane = threadIdx.x & 31;
    if (warp >= M) return;
    float* p = X + (size_t)warp * ld;
    float v[10];
    float sum = 0.f;
    #pragma unroll
    for (int k = 0; k < 10; k++) {
        int c = lane + 32 * k;
        v[k] = (c < DD) ? p[c] : 0.f;
        sum += v[k];
    }
    #pragma unroll
    for (int o = 16; o > 0; o >>= 1) sum += __shfl_xor_sync(0xFFFFFFFFu, sum, o);
    float mu = sum * (1.f / DD);
    float var = 0.f;
    #pragma unroll
    for (int k = 0; k < 10; k++) {
        int c = lane + 32 * k;
        float d = (c < DD) ? (v[k] - mu) : 0.f;
        var += d * d;
    }
    #pragma unroll
    for (int o = 16; o > 0; o >>= 1) var += __shfl_xor_sync(0xFFFFFFFFu, var, o);
    float rsig = rsqrtf(var * (1.f / DD) + 1e-5f);
    #pragma unroll
    for (int k = 0; k < 10; k++) {
        int c = lane + 32 * k;
        if (c < DD) p[c] = (v[k] - mu) * rsig * gamma[c] + beta[c];
    }
}

// in-place LN on the two fp16 halves of each mrg row; zero pad cols [600,640)
__global__ void ln_mrg_kernel(const float* __restrict__ g0, const float* __restrict__ b0,
                              const float* __restrict__ g1, const float* __restrict__ b1) {
    int warp = (int)((blockIdx.x * (long)blockDim.x + threadIdx.x) >> 5);
    int lane = threadIdx.x & 31;
    if (warp >= NN) return;
    size_t orow = (size_t)warp * KPM;
    #pragma unroll
    for (int half = 0; half < 2; half++) {
        fp16* p = g_mrg + orow + half * DD;
        const float* gamma = half ? g1 : g0;
        const float* beta  = half ? b1 : b0;
        float v[10];
        float sum = 0.f;
        #pragma unroll
        for (int k = 0; k < 10; k++) {
            int c = lane + 32 * k;
            v[k] = (c < DD) ? __half2float(p[c]) : 0.f;
            sum += v[k];
        }
        #pragma unroll
        for (int o = 16; o > 0; o >>= 1) sum += __shfl_xor_sync(0xFFFFFFFFu, sum, o);
        float mu = sum * (1.f / DD);
        float var = 0.f;
        #pragma unroll
        for (int k = 0; k < 10; k++) {
            int c = lane + 32 * k;
            float d = (c < DD) ? (v[k] - mu) : 0.f;
            var += d * d;
        }
        #pragma unroll
        for (int o = 16; o > 0; o >>= 1) var += __shfl_xor_sync(0xFFFFFFFFu, var, o);
        float rsig = rsqrtf(var * (1.f / DD) + 1e-5f);
        #pragma unroll
        for (int k = 0; k < 10; k++) {
            int c = lane + 32 * k;
            if (c < DD)
                p[c] = __float2half((v[k] - mu) * rsig * gamma[c] + beta[c]);
        }
    }
    fp16 z = __float2half(0.f);
    g_mrg[orow + 600 + lane] = z;
    if (lane < 8) g_mrg[orow + 632 + lane] = z;
}

// ---------------- launch ----------------------------------------------------
extern "C" void kernel_launch(void* const* d_in, const int* in_sizes, int n_in,
                              void* d_out, int out_size) {
    const float* x    = (const float*)d_in[0];
    const int*   er   = (const int*)d_in[1];
    const int*   ec   = (const int*)d_in[2];
    const float* Wr   = (const float*)d_in[3];
    const float* br   = (const float*)d_in[4];
    const float* Wc   = (const float*)d_in[5];
    const float* bc   = (const float*)d_in[6];
    const float* Wrs  = (const float*)d_in[7];
    const float* brs  = (const float*)d_in[8];
    const float* g_rs = (const float*)d_in[9];
    const float* b_rs = (const float*)d_in[10];
    const float* Wcs  = (const float*)d_in[11];
    const float* bcs  = (const float*)d_in[12];
    const float* g_cs = (const float*)d_in[13];
    const float* b_cs = (const float*)d_in[14];
    const float* Wm   = (const float*)d_in[15];
    const float* bm   = (const float*)d_in[16];
    const float* g_m  = (const float*)d_in[17];
    const float* b_m  = (const float*)d_in[18];
    float* out = (float*)d_out;

    float* deg;
    cudaGetSymbolAddress((void**)&deg, g_deg);
    int *off_r, *off_c, *cur_r, *cur_c, *csr_r, *csr_c;
    cudaGetSymbolAddress((void**)&off_r, g_off_r);
    cudaGetSymbolAddress((void**)&off_c, g_off_c);
    cudaGetSymbolAddress((void**)&cur_r, g_cur_r);
    cudaGetSymbolAddress((void**)&cur_c, g_cur_c);
    cudaGetSymbolAddress((void**)&csr_r, g_csr_r);
    cudaGetSymbolAddress((void**)&csr_c, g_csr_c);

    fp16 *aggr, *aggc, *rowg, *colg, *mrg;
    fp16 *pWr, *pWc, *pWrs, *pWcs, *pWm;
    cudaGetSymbolAddress((void**)&aggr, g_aggr);
    cudaGetSymbolAddress((void**)&aggc, g_aggc);
    cudaGetSymbolAddress((void**)&rowg, g_rowg);
    cudaGetSymbolAddress((void**)&colg, g_colg);
    cudaGetSymbolAddress((void**)&mrg,  g_mrg);
    cudaGetSymbolAddress((void**)&pWr,  g_Wr);
    cudaGetSymbolAddress((void**)&pWc,  g_Wc);
    cudaGetSymbolAddress((void**)&pWrs, g_Wrs);
    cudaGetSymbolAddress((void**)&pWcs, g_Wcs);
    cudaGetSymbolAddress((void**)&pWm,  g_Wm);

    cudaFuncSetAttribute(gemm_tc2_kernel,
                         cudaFuncAttributeMaxDynamicSharedMemorySize, SMEM_GEMM);

    // graph preprocessing + x conversion
    zero_ideg_kernel<<<(4 * NN + 255) / 256, 256>>>();
    degree_kernel<<<(NE + 255) / 256, 256>>>(er, ec);
    x_convert_kernel<<<(int)(((long)NN * DD / 2 + 255) / 256), 256>>>((const float2*)x);
    norm_kernel<<<(4 * NN + 255) / 256, 256>>>();
    dim3 sgrid(NSB, 2);
    scan1_kernel<<<sgrid, SB>>>();
    scan2_kernel<<<1, 256>>>(off_r, off_c);
    scan3_kernel<<<sgrid, SB>>>(off_r, cur_r, off_c, cur_c);
    fill_kernel<<<(NE + 255) / 256, 256>>>(er, cur_r, csr_r);
    fill_kernel<<<(NE + 255) / 256, 256>>>(ec, cur_c, csr_c);
    int ggrid = (NN * 32 + 255) / 256;
    gather_kernel<<<ggrid, 256>>>(csr_r, off_r, deg + 0 * NN, deg + 1 * NN, aggr);
    gather_kernel<<<ggrid, 256>>>(csr_c, off_c, deg + 2 * NN, deg + 3 * NN, aggc);
    tail_zero_kernel<<<((MP - NN) * KPM + 255) / 256, 256>>>();

    // weight converts
    int wgrid = (KP1 * NP + 255) / 256;
    w_convert_kernel<<<wgrid, 256>>>(Wr,  DD, DD, KP1, pWr);
    w_convert_kernel<<<wgrid, 256>>>(Wc,  DD, DD, KP1, pWc);
    w_convert_kernel<<<wgrid, 256>>>(Wrs, DD, DD, KP1, pWrs);
    w_convert_kernel<<<wgrid, 256>>>(Wcs, DD, DD, KP1, pWcs);
    w_convert_kernel<<<(KPM * NP + 255) / 256, 256>>>(Wm, 2 * DD, DD, KPM, pWm);

    dim3 gg(NP / GBN, MP / GBM);   // (5, 782)
    const int nK1 = KP1 / GBK;     // 5
    const int nKm = KPM / GBK;     // 10

    // GraphConv GEMMs: relu -> fp16 planes (zero-filled padding)
    gemm_tc2_kernel<<<gg, 256, SMEM_GEMM>>>(aggr, KP1, pWr, br,
        NN, DD, nK1, 1, 1, nullptr, 0, rowg, KP1);
    gemm_tc2_kernel<<<gg, 256, SMEM_GEMM>>>(aggc, KP1, pWc, bc,
        NN, DD, nK1, 1, 1, nullptr, 0, colg, KP1);

    // support GEMMs -> fp16 mrg halves directly (mode 2: valid-only stores)
    gemm_tc2_kernel<<<gg, 256, SMEM_GEMM>>>(rowg, KP1, pWrs, brs,
        NN, DD, nK1, 2, 0, nullptr, 0, mrg, KPM);
    gemm_tc2_kernel<<<gg, 256, SMEM_GEMM>>>(colg, KP1, pWcs, bcs,
        NN, DD, nK1, 2, 0, nullptr, 0, mrg + DD, KPM);

    // in-place fp16 LN on both halves (+ zero pad cols)
    int lngrid = (NN + 7) / 8;
    ln_mrg_kernel<<<lngrid, 256>>>(g_rs, b_rs, g_cs, b_cs);

    // merge GEMM (K=640) -> fp32 out, then final LN
    gemm_tc2_kernel<<<gg, 256, SMEM_GEMM>>>(mrg, KPM, pWm, bm,
        NN, DD, nKm, 0, 0, out, DD, nullptr, 0);
    ln_kernel<<<lngrid, 256>>>(out, DD, g_m, b_m, NN);
}

// round 15
// speedup vs baseline: 1.0663x; 1.0135x over previous
#include <cuda_runtime.h>
#include <cuda_fp16.h>
#include <cstddef>
#include <cstdint>

#define NN 100000
#define NE 1000000
#define DD 300
#define MP 100096      // NN padded to 128
#define KP1 320        // K=300 padded
#define NP  320        // N=300 padded
#define KPM 640        // merge K=600 padded

typedef __half fp16;
typedef __half2 fp162;

// ---------------- scratch (device globals; no allocation allowed) ----------
__device__ int   g_ideg[4 * NN];
__device__ float g_deg[4 * NN];
__device__ int   g_off_r[NN + 1], g_off_c[NN + 1];
__device__ int   g_cur_r[NN],     g_cur_c[NN];
__device__ int   g_csr_r[NE],     g_csr_c[NE];

#define SB 1024
#define NSB ((NN + SB - 1) / SB)   // 98
__device__ int g_bsum[2][NSB];
__device__ int g_boff[2][NSB];

// fp16 feature table (NN x DD)
__device__ __align__(16) fp16 g_xh[(size_t)NN * DD];
// fp16 operand planes (padded, M x K row-major)
__device__ __align__(16) fp16 g_aggr[(size_t)MP * KP1];
__device__ __align__(16) fp16 g_aggc[(size_t)MP * KP1];
__device__ __align__(16) fp16 g_rowg[(size_t)MP * KP1];
__device__ __align__(16) fp16 g_colg[(size_t)MP * KP1];
__device__ __align__(16) fp16 g_mrg[(size_t)MP * KPM];
// weight planes (single fp16): K x N row-major
__device__ __align__(16) fp16 g_Wr[KP1 * NP];
__device__ __align__(16) fp16 g_Wc[KP1 * NP];
__device__ __align__(16) fp16 g_Wrs[KP1 * NP];
__device__ __align__(16) fp16 g_Wcs[KP1 * NP];
__device__ __align__(16) fp16 g_Wm[KPM * NP];

// ---------------- helpers ----------------------------------------------------
__device__ __forceinline__ uint32_t pack2(fp16 a, fp16 b) {
    fp162 t = __halves2half2(a, b);
    return *(uint32_t*)&t;
}
#define SWZ(x) ((x) ^ (((x) >> 3) & 0x70))
__device__ __forceinline__ void cp16(uint32_t dst, const void* src) {
    asm volatile("cp.async.cg.shared.global [%0], [%1], 16;" :: "r"(dst), "l"(src));
}
__device__ __forceinline__ void ldsm_x4(uint32_t& r0, uint32_t& r1, uint32_t& r2, uint32_t& r3,
                                        uint32_t addr) {
    asm volatile("ldmatrix.sync.aligned.m8n8.x4.shared.b16 {%0,%1,%2,%3}, [%4];"
                 : "=r"(r0), "=r"(r1), "=r"(r2), "=r"(r3) : "r"(addr));
}
__device__ __forceinline__ void ldsm_x4_t(uint32_t& r0, uint32_t& r1, uint32_t& r2, uint32_t& r3,
                                          uint32_t addr) {
    asm volatile("ldmatrix.sync.aligned.m8n8.x4.trans.shared.b16 {%0,%1,%2,%3}, [%4];"
                 : "=r"(r0), "=r"(r1), "=r"(r2), "=r"(r3) : "r"(addr));
}
__device__ __forceinline__ void mma_fp16(float* c, const uint32_t* a, const uint32_t* b) {
    asm volatile("mma.sync.aligned.m16n8k16.row.col.f32.f16.f16.f32 "
                 "{%0,%1,%2,%3}, {%4,%5,%6,%7}, {%8,%9}, {%0,%1,%2,%3};"
                 : "+f"(c[0]), "+f"(c[1]), "+f"(c[2]), "+f"(c[3])
                 : "r"(a[0]), "r"(a[1]), "r"(a[2]), "r"(a[3]), "r"(b[0]), "r"(b[1]));
}

// ---------------- graph preprocessing ----------------------------------------
__global__ void degree_kernel(const int* __restrict__ er, const int* __restrict__ ec) {
    int i = blockIdx.x * blockDim.x + threadIdx.x;
    if (i < NE) {
        atomicAdd(&g_ideg[0 * NN + er[i]],      1);
        atomicAdd(&g_ideg[1 * NN + er[NE + i]], 1);
        atomicAdd(&g_ideg[2 * NN + ec[i]],      1);
        atomicAdd(&g_ideg[3 * NN + ec[NE + i]], 1);
    }
}

// fused: degree->rsqrt norms AND x fp32 -> fp16 table
__global__ void normx_kernel(const float2* __restrict__ x) {
    long i = (long)blockIdx.x * blockDim.x + threadIdx.x;
    if (i < 4 * NN) {
        int d = g_ideg[i];
        g_deg[i] = (d > 0) ? rsqrtf((float)d) : 0.f;
    }
    if (i < (long)NN * DD / 2) {
        float2 v = x[i];
        *(uint32_t*)&g_xh[i * 2] = pack2(__float2half(v.x), __float2half(v.y));
    }
}

__global__ __launch_bounds__(SB) void scan1_kernel() {
    int gsel = blockIdx.y;
    const int* deg = g_ideg + (gsel ? 3 : 1) * NN;
    int i = blockIdx.x * SB + threadIdx.x;
    int v = (i < NN) ? deg[i] : 0;
    __shared__ int ws[32];
    #pragma unroll
    for (int o = 16; o > 0; o >>= 1) v += __shfl_xor_sync(0xFFFFFFFFu, v, o);
    if ((threadIdx.x & 31) == 0) ws[threadIdx.x >> 5] = v;
    __syncthreads();
    if (threadIdx.x < 32) {
        int s = (threadIdx.x < SB / 32) ? ws[threadIdx.x] : 0;
        #pragma unroll
        for (int o = 16; o > 0; o >>= 1) s += __shfl_xor_sync(0xFFFFFFFFu, s, o);
        if (threadIdx.x == 0) g_bsum[gsel][blockIdx.x] = s;
    }
}

__global__ __launch_bounds__(256) void scan2_kernel(int* __restrict__ off_r,
                                                    int* __restrict__ off_c) {
    __shared__ int ss[2][128];
    int t = threadIdx.x;
    int h = t >> 7;
    int j = t & 127;
    int v = (j < NSB) ? g_bsum[h][j] : 0;
    ss[h][j] = v;
    __syncthreads();
    #pragma unroll
    for (int d = 1; d < 128; d <<= 1) {
        int u = (j >= d) ? ss[h][j - d] : 0;
        __syncthreads();
        ss[h][j] += u;
        __syncthreads();
    }
    if (j < NSB) g_boff[h][j] = ss[h][j] - v;
    if (t == 0) { off_r[NN] = NE; off_c[NN] = NE; }
}

__global__ __launch_bounds__(SB) void scan3_kernel(int* __restrict__ off_r,
                                                   int* __restrict__ cur_r,
                                                   int* __restrict__ off_c,
                                                   int* __restrict__ cur_c) {
    int gsel = blockIdx.y;
    const int* deg = g_ideg + (gsel ? 3 : 1) * NN;
    int* off = gsel ? off_c : off_r;
    int* cur = gsel ? cur_c : cur_r;
    __shared__ int ss[SB];
    int i = blockIdx.x * SB + threadIdx.x;
    int v = (i < NN) ? deg[i] : 0;
    ss[threadIdx.x] = v;
    __syncthreads();
    #pragma unroll
    for (int d = 1; d < SB; d <<= 1) {
        int u = (threadIdx.x >= d) ? ss[threadIdx.x - d] : 0;
        __syncthreads();
        ss[threadIdx.x] += u;
        __syncthreads();
    }
    if (i < NN) {
        int excl = ss[threadIdx.x] - v + g_boff[gsel][blockIdx.x];
        off[i] = excl;
        cur[i] = excl;
    }
}

// fused fill: blockIdx.y selects graph
__global__ void fill2_kernel(const int* __restrict__ er, const int* __restrict__ ec,
                             int* __restrict__ cur_r, int* __restrict__ cur_c,
                             int* __restrict__ csr_r, int* __restrict__ csr_c) {
    int i = blockIdx.x * blockDim.x + threadIdx.x;
    const int* edges = blockIdx.y ? ec : er;
    int* cur = blockIdx.y ? cur_c : cur_r;
    int* csr = blockIdx.y ? csr_c : csr_r;
    if (i < NE) {
        int s = edges[i];
        int d = edges[NE + i];
        int pos = atomicAdd(&cur[d], 1);
        csr[pos] = s;
    }
}

// fused gather: blockIdx.y selects graph. one warp per node; fp16 x reads.
__global__ __launch_bounds__(256) void gather2_kernel(
    const int* __restrict__ csr_r, const int* __restrict__ csr_c,
    const int* __restrict__ off_r, const int* __restrict__ off_c,
    const float* __restrict__ deg) {
    int gsel = blockIdx.y;
    const int* csr = gsel ? csr_c : csr_r;
    const int* off = gsel ? off_c : off_r;
    const float* nsrc = deg + (gsel ? 2 : 0) * NN;
    const float* ndst = deg + (gsel ? 3 : 1) * NN;
    fp16* Ah = gsel ? g_aggc : g_aggr;

    int warp = (int)((blockIdx.x * (long)blockDim.x + threadIdx.x) >> 5);
    int lane = threadIdx.x & 31;
    if (warp >= NN) return;
    int o0 = off[warp], o1 = off[warp + 1];
    float4 a0 = make_float4(0.f, 0.f, 0.f, 0.f);
    float4 a1 = a0, a2 = a0;
    for (int j = o0; j < o1; j++) {
        int s = csr[j];
        float ns = nsrc[s];
        const uint2* xr = (const uint2*)(g_xh + (size_t)s * DD);
        uint2 u = xr[lane];
        float2 p0 = __half22float2(*(fp162*)&u.x);
        float2 p1 = __half22float2(*(fp162*)&u.y);
        a0.x += p0.x * ns; a0.y += p0.y * ns; a0.z += p1.x * ns; a0.w += p1.y * ns;
        u = xr[32 + lane];
        p0 = __half22float2(*(fp162*)&u.x);
        p1 = __half22float2(*(fp162*)&u.y);
        a1.x += p0.x * ns; a1.y += p0.y * ns; a1.z += p1.x * ns; a1.w += p1.y * ns;
        if (lane < 11) {
            u = xr[64 + lane];
            p0 = __half22float2(*(fp162*)&u.x);
            p1 = __half22float2(*(fp162*)&u.y);
            a2.x += p0.x * ns; a2.y += p0.y * ns; a2.z += p1.x * ns; a2.w += p1.y * ns;
        }
    }
    float nd = ndst[warp];
    size_t orow = (size_t)warp * KP1;
    auto store4 = [&](float4 a, int f4i) {
        uint2 hh = make_uint2(
            pack2(__float2half(a.x * nd), __float2half(a.y * nd)),
            pack2(__float2half(a.z * nd), __float2half(a.w * nd)));
        *(uint2*)&Ah[orow + f4i * 4] = hh;
    };
    store4(a0, lane);
    store4(a1, 32 + lane);
    if (lane < 11) store4(a2, 64 + lane);
    if (lane < 20) Ah[orow + 300 + lane] = __float2half(0.f);
}

// weight (K x Ncols fp32) -> fp16 plane (KPp x NP), zero padded
__global__ void w_convert_kernel(const float* __restrict__ W, int K, int Ncols, int KPp,
                                 fp16* __restrict__ Wh) {
    int idx = blockIdx.x * blockDim.x + threadIdx.x;
    if (idx >= KPp * NP) return;
    int k = idx / NP;
    int n = idx - k * NP;
    float v = (k < K && n < Ncols) ? W[(size_t)k * Ncols + n] : 0.f;
    Wh[idx] = __float2half(v);
}

// ====== Tensor-core GEMM: fp16 single-pass, SW128, GBK=64, 3-stage ==========
// mode 0: fp32 out (guarded). mode 1: fp16 plane, zero-fill full padded tile.
// mode 2: fp16 out, store ONLY valid elements (for aliased mrg halves).
#define GBM 128
#define GBN 64
#define GBK 64
#define A_PL 16384u
#define B_PL 8192u
#define STG (A_PL + B_PL)           // 24576
#define NSTAGE 3
#define SMEM_GEMM (NSTAGE * STG)    // 73728

__global__ __launch_bounds__(256) void gemm_tc2_kernel(
    const fp16* __restrict__ Ap, int lda,
    const fp16* __restrict__ Bp,
    const float* __restrict__ bias,
    int M, int Ncols, int nK, int mode, int relu,
    float* __restrict__ Cf, int ldc,
    fp16* __restrict__ Ch, int ldcp)
{
    extern __shared__ __align__(128) char smem[];
    const uint32_t sb = (uint32_t)__cvta_generic_to_shared(smem);

    const int t = threadIdx.x;
    const int wid = t >> 5;
    const int lane = t & 31;
    const int warp_m = wid >> 1;
    const int warp_n = wid & 1;
    const int m0 = blockIdx.y * GBM;
    const int n0 = blockIdx.x * GBN;

    float acc[2][4][4];
    #pragma unroll
    for (int mi = 0; mi < 2; mi++)
        #pragma unroll
        for (int ni = 0; ni < 4; ni++)
            #pragma unroll
            for (int j = 0; j < 4; j++) acc[mi][ni][j] = 0.f;

    auto load_stage = [&](int stage, int k0) {
        const uint32_t base = sb + (uint32_t)stage * STG;
        const uint32_t aA = base;
        const uint32_t aB = base + A_PL;
        #pragma unroll
        for (int i = 0; i < 4; i++) {
            int idx = i * 256 + t;
            int r = idx >> 3, c = idx & 7;
            uint32_t d = SWZ((uint32_t)(r * 128 + c * 16));
            cp16(aA + d, Ap + (size_t)(m0 + r) * lda + k0 + c * 8);
        }
        #pragma unroll
        for (int i = 0; i < 2; i++) {
            int idx = i * 256 + t;
            int r = idx >> 3, c = idx & 7;
            uint32_t d = SWZ((uint32_t)(r * 128 + c * 16));
            cp16(aB + d, Bp + (size_t)(k0 + r) * NP + n0 + c * 8);
        }
        asm volatile("cp.async.commit_group;");
    };

    // prologue: two stages in flight
    load_stage(0, 0);
    if (nK > 1) load_stage(1, GBK);

    const int lrow = lane & 15;
    const int lhi = lane >> 4;

    int stage = 0;
    for (int kt = 0; kt < nK; kt++) {
        if (kt + 2 < nK) {
            int s2 = stage + 2; if (s2 >= NSTAGE) s2 -= NSTAGE;
            load_stage(s2, (kt + 2) * GBK);
            asm volatile("cp.async.wait_group 2;");
        } else if (kt + 1 < nK) {
            asm volatile("cp.async.wait_group 1;");
        } else {
            asm volatile("cp.async.wait_group 0;");
        }
        __syncthreads();

        const uint32_t base = sb + (uint32_t)stage * STG;
        const uint32_t aA = base;
        const uint32_t aB = base + A_PL;

        #pragma unroll
        for (int ks = 0; ks < 4; ks++) {
            uint32_t ah[2][4];
            #pragma unroll
            for (int mi = 0; mi < 2; mi++) {
                int row = warp_m * 32 + mi * 16 + lrow;
                uint32_t off = SWZ((uint32_t)(row * 128 + ks * 32 + lhi * 16));
                ldsm_x4(ah[mi][0], ah[mi][1], ah[mi][2], ah[mi][3], aA + off);
            }
            uint32_t bh[4][2];
            #pragma unroll
            for (int nj = 0; nj < 2; nj++) {
                int krow = ks * 16 + lrow;
                uint32_t off = SWZ((uint32_t)(krow * 128 + warp_n * 64 + nj * 32 + lhi * 16));
                uint32_t r0, r1, r2, r3;
                ldsm_x4_t(r0, r1, r2, r3, aB + off);
                bh[nj * 2 + 0][0] = r0; bh[nj * 2 + 0][1] = r1;
                bh[nj * 2 + 1][0] = r2; bh[nj * 2 + 1][1] = r3;
            }
            #pragma unroll
            for (int mi = 0; mi < 2; mi++)
                #pragma unroll
                for (int ni = 0; ni < 4; ni++)
                    mma_fp16(acc[mi][ni], ah[mi], bh[ni]);
        }
        __syncthreads();
        stage++; if (stage >= NSTAGE) stage = 0;
    }

    // ---- epilogue ----
    const int g = lane >> 2;
    const int tig = lane & 3;
    #pragma unroll
    for (int mi = 0; mi < 2; mi++) {
        #pragma unroll
        for (int ni = 0; ni < 4; ni++) {
            int col = n0 + warp_n * 32 + ni * 8 + tig * 2;
            float bx = 0.f, by = 0.f;
            if (bias != nullptr && col < Ncols) {
                bx = bias[col];
                if (col + 1 < Ncols) by = bias[col + 1];
            }
            #pragma unroll
            for (int rr = 0; rr < 2; rr++) {
                int row = m0 + warp_m * 32 + mi * 16 + g + rr * 8;
                float vx = acc[mi][ni][rr * 2 + 0] + bx;
                float vy = acc[mi][ni][rr * 2 + 1] + by;
                if (relu) { vx = fmaxf(vx, 0.f); vy = fmaxf(vy, 0.f); }
                bool ok = (row < M) && (col < Ncols);
                if (mode == 0) {
                    if (ok)
                        *(float2*)(Cf + (size_t)row * ldc + col) = make_float2(vx, vy);
                } else if (mode == 1) {
                    if (!ok) { vx = 0.f; vy = 0.f; }
                    *(uint32_t*)&Ch[(size_t)row * ldcp + col] =
                        pack2(__float2half(vx), __float2half(vy));
                } else {
                    if (ok)
                        *(uint32_t*)&Ch[(size_t)row * ldcp + col] =
                            pack2(__float2half(vx), __float2half(vy));
                }
            }
        }
    }
}

// ---------------- LayerNorm (fp32, in place) --------------------------------
__global__ void ln_kernel(float* __restrict__ X, int ld,
                          const float* __restrict__ gamma,
                          const float* __restrict__ beta, int M) {
    int warp = (int)((blockIdx.x * (long)blockDim.x + threadIdx.x) >> 5);
    int lane = threadIdx.x & 31;
    if (warp >= M) return;
    float* p = X + (size_t)warp * ld;
    float v[10];
    float sum = 0.f;
    #pragma unroll
    for (int k = 0; k < 10; k++) {
        int c = lane + 32 * k;
        v[k] = (c < DD) ? p[c] : 0.f;
        sum += v[k];
    }
    #pragma unroll
    for (int o = 16; o > 0; o >>= 1) sum += __shfl_xor_sync(0xFFFFFFFFu, sum, o);
    float mu = sum * (1.f / DD);
    float var = 0.f;
    #pragma unroll
    for (int k = 0; k < 10; k++) {
        int c = lane + 32 * k;
        float d = (c < DD) ? (v[k] - mu) : 0.f;
        var += d * d;
    }
    #pragma unroll
    for (int o = 16; o > 0; o >>= 1) var += __shfl_xor_sync(0xFFFFFFFFu, var, o);
    float rsig = rsqrtf(var * (1.f / DD) + 1e-5f);
    #pragma unroll
    for (int k = 0; k < 10; k++) {
        int c = lane + 32 * k;
        if (c < DD) p[c] = (v[k] - mu) * rsig * gamma[c] + beta[c];
    }
}

// in-place LN on the two fp16 halves of each mrg row; zero pad cols [600,640)
__global__ void ln_mrg_kernel(const float* __restrict__ g0, const float* __restrict__ b0,
                              const float* __restrict__ g1, const float* __restrict__ b1) {
    int warp = (int)((blockIdx.x * (long)blockDim.x + threadIdx.x) >> 5);
    int lane = threadIdx.x & 31;
    if (warp >= NN) return;
    size_t orow = (size_t)warp * KPM;
    #pragma unroll
    for (int half = 0; half < 2; half++) {
        fp16* p = g_mrg + orow + half * DD;
        const float* gamma = half ? g1 : g0;
        const float* beta  = half ? b1 : b0;
        float v[10];
        float sum = 0.f;
        #pragma unroll
        for (int k = 0; k < 10; k++) {
            int c = lane + 32 * k;
            v[k] = (c < DD) ? __half2float(p[c]) : 0.f;
            sum += v[k];
        }
        #pragma unroll
        for (int o = 16; o > 0; o >>= 1) sum += __shfl_xor_sync(0xFFFFFFFFu, sum, o);
        float mu = sum * (1.f / DD);
        float var = 0.f;
        #pragma unroll
        for (int k = 0; k < 10; k++) {
            int c = lane + 32 * k;
            float d = (c < DD) ? (v[k] - mu) : 0.f;
            var += d * d;
        }
        #pragma unroll
        for (int o = 16; o > 0; o >>= 1) var += __shfl_xor_sync(0xFFFFFFFFu, var, o);
        float rsig = rsqrtf(var * (1.f / DD) + 1e-5f);
        #pragma unroll
        for (int k = 0; k < 10; k++) {
            int c = lane + 32 * k;
            if (c < DD)
                p[c] = __float2half((v[k] - mu) * rsig * gamma[c] + beta[c]);
        }
    }
    fp16 z = __float2half(0.f);
    g_mrg[orow + 600 + lane] = z;
    if (lane < 8) g_mrg[orow + 632 + lane] = z;
}

// ---------------- launch ----------------------------------------------------
extern "C" void kernel_launch(void* const* d_in, const int* in_sizes, int n_in,
                              void* d_out, int out_size) {
    const float* x    = (const float*)d_in[0];
    const int*   er   = (const int*)d_in[1];
    const int*   ec   = (const int*)d_in[2];
    const float* Wr   = (const float*)d_in[3];
    const float* br   = (const float*)d_in[4];
    const float* Wc   = (const float*)d_in[5];
    const float* bc   = (const float*)d_in[6];
    const float* Wrs  = (const float*)d_in[7];
    const float* brs  = (const float*)d_in[8];
    const float* g_rs = (const float*)d_in[9];
    const float* b_rs = (const float*)d_in[10];
    const float* Wcs  = (const float*)d_in[11];
    const float* bcs  = (const float*)d_in[12];
    const float* g_cs = (const float*)d_in[13];
    const float* b_cs = (const float*)d_in[14];
    const float* Wm   = (const float*)d_in[15];
    const float* bm   = (const float*)d_in[16];
    const float* g_m  = (const float*)d_in[17];
    const float* b_m  = (const float*)d_in[18];
    float* out = (float*)d_out;

    float* deg;
    cudaGetSymbolAddress((void**)&deg, g_deg);
    int *ideg, *off_r, *off_c, *cur_r, *cur_c, *csr_r, *csr_c;
    cudaGetSymbolAddress((void**)&ideg,  g_ideg);
    cudaGetSymbolAddress((void**)&off_r, g_off_r);
    cudaGetSymbolAddress((void**)&off_c, g_off_c);
    cudaGetSymbolAddress((void**)&cur_r, g_cur_r);
    cudaGetSymbolAddress((void**)&cur_c, g_cur_c);
    cudaGetSymbolAddress((void**)&csr_r, g_csr_r);
    cudaGetSymbolAddress((void**)&csr_c, g_csr_c);

    fp16 *aggr, *aggc, *rowg, *colg, *mrg;
    fp16 *pWr, *pWc, *pWrs, *pWcs, *pWm;
    cudaGetSymbolAddress((void**)&aggr, g_aggr);
    cudaGetSymbolAddress((void**)&aggc, g_aggc);
    cudaGetSymbolAddress((void**)&rowg, g_rowg);
    cudaGetSymbolAddress((void**)&colg, g_colg);
    cudaGetSymbolAddress((void**)&mrg,  g_mrg);
    cudaGetSymbolAddress((void**)&pWr,  g_Wr);
    cudaGetSymbolAddress((void**)&pWc,  g_Wc);
    cudaGetSymbolAddress((void**)&pWrs, g_Wrs);
    cudaGetSymbolAddress((void**)&pWcs, g_Wcs);
    cudaGetSymbolAddress((void**)&pWm,  g_Wm);

    cudaFuncSetAttribute(gemm_tc2_kernel,
                         cudaFuncAttributeMaxDynamicSharedMemorySize, SMEM_GEMM);

    // graph preprocessing (memsets replace zero kernels)
    cudaMemsetAsync(ideg, 0, 4 * NN * sizeof(int));
    // zero tail rows of agg + mrg planes (fp16 zero == 0x0000)
    cudaMemsetAsync(aggr + (size_t)NN * KP1, 0, (size_t)(MP - NN) * KP1 * sizeof(fp16));
    cudaMemsetAsync(aggc + (size_t)NN * KP1, 0, (size_t)(MP - NN) * KP1 * sizeof(fp16));
    cudaMemsetAsync(mrg  + (size_t)NN * KPM, 0, (size_t)(MP - NN) * KPM * sizeof(fp16));

    degree_kernel<<<(NE + 255) / 256, 256>>>(er, ec);
    normx_kernel<<<(int)(((long)NN * DD / 2 + 255) / 256), 256>>>((const float2*)x);
    dim3 sgrid(NSB, 2);
    scan1_kernel<<<sgrid, SB>>>();
    scan2_kernel<<<1, 256>>>(off_r, off_c);
    scan3_kernel<<<sgrid, SB>>>(off_r, cur_r, off_c, cur_c);
    dim3 fgrid((NE + 255) / 256, 2);
    fill2_kernel<<<fgrid, 256>>>(er, ec, cur_r, cur_c, csr_r, csr_c);
    dim3 ggrid2((NN * 32 + 255) / 256, 2);
    gather2_kernel<<<ggrid2, 256>>>(csr_r, csr_c, off_r, off_c, deg);

    // weight converts
    int wgrid = (KP1 * NP + 255) / 256;
    w_convert_kernel<<<wgrid, 256>>>(Wr,  DD, DD, KP1, pWr);
    w_convert_kernel<<<wgrid, 256>>>(Wc,  DD, DD, KP1, pWc);
    w_convert_kernel<<<wgrid, 256>>>(Wrs, DD, DD, KP1, pWrs);
    w_convert_kernel<<<wgrid, 256>>>(Wcs, DD, DD, KP1, pWcs);
    w_convert_kernel<<<(KPM * NP + 255) / 256, 256>>>(Wm, 2 * DD, DD, KPM, pWm);

    dim3 gg(NP / GBN, MP / GBM);   // (5, 782)
    const int nK1 = KP1 / GBK;     // 5
    const int nKm = KPM / GBK;     // 10

    // GraphConv GEMMs: relu -> fp16 planes (zero-filled padding)
    gemm_tc2_kernel<<<gg, 256, SMEM_GEMM>>>(aggr, KP1, pWr, br,
        NN, DD, nK1, 1, 1, nullptr, 0, rowg, KP1);
    gemm_tc2_kernel<<<gg, 256, SMEM_GEMM>>>(aggc, KP1, pWc, bc,
        NN, DD, nK1, 1, 1, nullptr, 0, colg, KP1);

    // support GEMMs -> fp16 mrg halves directly (mode 2: valid-only stores)
    gemm_tc2_kernel<<<gg, 256, SMEM_GEMM>>>(rowg, KP1, pWrs, brs,
        NN, DD, nK1, 2, 0, nullptr, 0, mrg, KPM);
    gemm_tc2_kernel<<<gg, 256, SMEM_GEMM>>>(colg, KP1, pWcs, bcs,
        NN, DD, nK1, 2, 0, nullptr, 0, mrg + DD, KPM);

    // in-place fp16 LN on both halves (+ zero pad cols)
    int lngrid = (NN + 7) / 8;
    ln_mrg_kernel<<<lngrid, 256>>>(g_rs, b_rs, g_cs, b_cs);

    // merge GEMM (K=640) -> fp32 out, then final LN
    gemm_tc2_kernel<<<gg, 256, SMEM_GEMM>>>(mrg, KPM, pWm, bm,
        NN, DD, nKm, 0, 0, out, DD, nullptr, 0);
    ln_kernel<<<lngrid, 256>>>(out, DD, g_m, b_m, NN);
}

// round 16
// speedup vs baseline: 1.0722x; 1.0055x over previous
#include <cuda_runtime.h>
#include <cuda_fp16.h>
#include <cstddef>
#include <cstdint>

#define NN 100000
#define NE 1000000
#define DD 300
#define MP 100096      // NN padded to 128
#define KP1 320        // K=300 padded
#define NP  320        // N=300 padded
#define KPM 640        // merge K=600 padded

typedef __half fp16;
typedef __half2 fp162;

// ---------------- scratch (device globals; no allocation allowed) ----------
__device__ int   g_ideg[4 * NN];
__device__ float g_deg[4 * NN];
__device__ int   g_off_r[NN + 1], g_off_c[NN + 1];
__device__ int   g_cur_r[NN],     g_cur_c[NN];
__device__ int   g_csr_r[NE],     g_csr_c[NE];

#define SB 1024
#define NSB ((NN + SB - 1) / SB)   // 98
__device__ int g_bsum[2][NSB];
__device__ int g_boff[2][NSB];

// fp16 feature table (NN x DD)
__device__ __align__(16) fp16 g_xh[(size_t)NN * DD];
// fp16 operand planes (padded, M x K row-major)
__device__ __align__(16) fp16 g_aggr[(size_t)MP * KP1];
__device__ __align__(16) fp16 g_aggc[(size_t)MP * KP1];
__device__ __align__(16) fp16 g_rowg[(size_t)MP * KP1];
__device__ __align__(16) fp16 g_colg[(size_t)MP * KP1];
__device__ __align__(16) fp16 g_mrg[(size_t)MP * KPM];
// weight planes (single fp16): K x N row-major, CONTIGUOUS for fused convert:
// [Wr | Wc | Wrs | Wcs | Wm] = 4*KP1*NP + KPM*NP halves
#define WPL (KP1 * NP)             // 102400
__device__ __align__(16) fp16 g_W[4 * WPL + KPM * NP];

// ---------------- helpers ----------------------------------------------------
__device__ __forceinline__ uint32_t pack2(fp16 a, fp16 b) {
    fp162 t = __halves2half2(a, b);
    return *(uint32_t*)&t;
}
#define SWZ(x) ((x) ^ (((x) >> 3) & 0x70))
__device__ __forceinline__ void cp16(uint32_t dst, const void* src) {
    asm volatile("cp.async.cg.shared.global [%0], [%1], 16;" :: "r"(dst), "l"(src));
}
__device__ __forceinline__ void ldsm_x4(uint32_t& r0, uint32_t& r1, uint32_t& r2, uint32_t& r3,
                                        uint32_t addr) {
    asm volatile("ldmatrix.sync.aligned.m8n8.x4.shared.b16 {%0,%1,%2,%3}, [%4];"
                 : "=r"(r0), "=r"(r1), "=r"(r2), "=r"(r3) : "r"(addr));
}
__device__ __forceinline__ void ldsm_x4_t(uint32_t& r0, uint32_t& r1, uint32_t& r2, uint32_t& r3,
                                          uint32_t addr) {
    asm volatile("ldmatrix.sync.aligned.m8n8.x4.trans.shared.b16 {%0,%1,%2,%3}, [%4];"
                 : "=r"(r0), "=r"(r1), "=r"(r2), "=r"(r3) : "r"(addr));
}
__device__ __forceinline__ void mma_fp16(float* c, const uint32_t* a, const uint32_t* b) {
    asm volatile("mma.sync.aligned.m16n8k16.row.col.f32.f16.f16.f32 "
                 "{%0,%1,%2,%3}, {%4,%5,%6,%7}, {%8,%9}, {%0,%1,%2,%3};"
                 : "+f"(c[0]), "+f"(c[1]), "+f"(c[2]), "+f"(c[3])
                 : "r"(a[0]), "r"(a[1]), "r"(a[2]), "r"(a[3]), "r"(b[0]), "r"(b[1]));
}

// ---------------- graph preprocessing ----------------------------------------
__global__ void degree_kernel(const int* __restrict__ er, const int* __restrict__ ec) {
    int i = blockIdx.x * blockDim.x + threadIdx.x;
    if (i < NE) {
        atomicAdd(&g_ideg[0 * NN + er[i]],      1);
        atomicAdd(&g_ideg[1 * NN + er[NE + i]], 1);
        atomicAdd(&g_ideg[2 * NN + ec[i]],      1);
        atomicAdd(&g_ideg[3 * NN + ec[NE + i]], 1);
    }
}

// fused: degree->rsqrt norms AND x fp32 -> fp16 table
__global__ void normx_kernel(const float2* __restrict__ x) {
    long i = (long)blockIdx.x * blockDim.x + threadIdx.x;
    if (i < 4 * NN) {
        int d = g_ideg[i];
        g_deg[i] = (d > 0) ? rsqrtf((float)d) : 0.f;
    }
    if (i < (long)NN * DD / 2) {
        float2 v = x[i];
        *(uint32_t*)&g_xh[i * 2] = pack2(__float2half(v.x), __float2half(v.y));
    }
}

__global__ __launch_bounds__(SB) void scan1_kernel() {
    int gsel = blockIdx.y;
    const int* deg = g_ideg + (gsel ? 3 : 1) * NN;
    int i = blockIdx.x * SB + threadIdx.x;
    int v = (i < NN) ? deg[i] : 0;
    __shared__ int ws[32];
    #pragma unroll
    for (int o = 16; o > 0; o >>= 1) v += __shfl_xor_sync(0xFFFFFFFFu, v, o);
    if ((threadIdx.x & 31) == 0) ws[threadIdx.x >> 5] = v;
    __syncthreads();
    if (threadIdx.x < 32) {
        int s = (threadIdx.x < SB / 32) ? ws[threadIdx.x] : 0;
        #pragma unroll
        for (int o = 16; o > 0; o >>= 1) s += __shfl_xor_sync(0xFFFFFFFFu, s, o);
        if (threadIdx.x == 0) g_bsum[gsel][blockIdx.x] = s;
    }
}

__global__ __launch_bounds__(256) void scan2_kernel(int* __restrict__ off_r,
                                                    int* __restrict__ off_c) {
    __shared__ int ss[2][128];
    int t = threadIdx.x;
    int h = t >> 7;
    int j = t & 127;
    int v = (j < NSB) ? g_bsum[h][j] : 0;
    ss[h][j] = v;
    __syncthreads();
    #pragma unroll
    for (int d = 1; d < 128; d <<= 1) {
        int u = (j >= d) ? ss[h][j - d] : 0;
        __syncthreads();
        ss[h][j] += u;
        __syncthreads();
    }
    if (j < NSB) g_boff[h][j] = ss[h][j] - v;
    if (t == 0) { off_r[NN] = NE; off_c[NN] = NE; }
}

__global__ __launch_bounds__(SB) void scan3_kernel(int* __restrict__ off_r,
                                                   int* __restrict__ cur_r,
                                                   int* __restrict__ off_c,
                                                   int* __restrict__ cur_c) {
    int gsel = blockIdx.y;
    const int* deg = g_ideg + (gsel ? 3 : 1) * NN;
    int* off = gsel ? off_c : off_r;
    int* cur = gsel ? cur_c : cur_r;
    __shared__ int ss[SB];
    int i = blockIdx.x * SB + threadIdx.x;
    int v = (i < NN) ? deg[i] : 0;
    ss[threadIdx.x] = v;
    __syncthreads();
    #pragma unroll
    for (int d = 1; d < SB; d <<= 1) {
        int u = (threadIdx.x >= d) ? ss[threadIdx.x - d] : 0;
        __syncthreads();
        ss[threadIdx.x] += u;
        __syncthreads();
    }
    if (i < NN) {
        int excl = ss[threadIdx.x] - v + g_boff[gsel][blockIdx.x];
        off[i] = excl;
        cur[i] = excl;
    }
}

// fused fill: blockIdx.y selects graph
__global__ void fill2_kernel(const int* __restrict__ er, const int* __restrict__ ec,
                             int* __restrict__ cur_r, int* __restrict__ cur_c,
                             int* __restrict__ csr_r, int* __restrict__ csr_c) {
    int i = blockIdx.x * blockDim.x + threadIdx.x;
    const int* edges = blockIdx.y ? ec : er;
    int* cur = blockIdx.y ? cur_c : cur_r;
    int* csr = blockIdx.y ? csr_c : csr_r;
    if (i < NE) {
        int s = edges[i];
        int d = edges[NE + i];
        int pos = atomicAdd(&cur[d], 1);
        csr[pos] = s;
    }
}

// fused gather: blockIdx.y selects graph. one warp per node; fp16 x reads.
__global__ __launch_bounds__(256) void gather2_kernel(
    const int* __restrict__ csr_r, const int* __restrict__ csr_c,
    const int* __restrict__ off_r, const int* __restrict__ off_c,
    const float* __restrict__ deg) {
    int gsel = blockIdx.y;
    const int* csr = gsel ? csr_c : csr_r;
    const int* off = gsel ? off_c : off_r;
    const float* nsrc = deg + (gsel ? 2 : 0) * NN;
    const float* ndst = deg + (gsel ? 3 : 1) * NN;
    fp16* Ah = gsel ? g_aggc : g_aggr;

    int warp = (int)((blockIdx.x * (long)blockDim.x + threadIdx.x) >> 5);
    int lane = threadIdx.x & 31;
    if (warp >= NN) return;
    int o0 = off[warp], o1 = off[warp + 1];
    float4 a0 = make_float4(0.f, 0.f, 0.f, 0.f);
    float4 a1 = a0, a2 = a0;
    for (int j = o0; j < o1; j++) {
        int s = csr[j];
        float ns = nsrc[s];
        const uint2* xr = (const uint2*)(g_xh + (size_t)s * DD);
        uint2 u = xr[lane];
        float2 p0 = __half22float2(*(fp162*)&u.x);
        float2 p1 = __half22float2(*(fp162*)&u.y);
        a0.x += p0.x * ns; a0.y += p0.y * ns; a0.z += p1.x * ns; a0.w += p1.y * ns;
        u = xr[32 + lane];
        p0 = __half22float2(*(fp162*)&u.x);
        p1 = __half22float2(*(fp162*)&u.y);
        a1.x += p0.x * ns; a1.y += p0.y * ns; a1.z += p1.x * ns; a1.w += p1.y * ns;
        if (lane < 11) {
            u = xr[64 + lane];
            p0 = __half22float2(*(fp162*)&u.x);
            p1 = __half22float2(*(fp162*)&u.y);
            a2.x += p0.x * ns; a2.y += p0.y * ns; a2.z += p1.x * ns; a2.w += p1.y * ns;
        }
    }
    float nd = ndst[warp];
    size_t orow = (size_t)warp * KP1;
    auto store4 = [&](float4 a, int f4i) {
        uint2 hh = make_uint2(
            pack2(__float2half(a.x * nd), __float2half(a.y * nd)),
            pack2(__float2half(a.z * nd), __float2half(a.w * nd)));
        *(uint2*)&Ah[orow + f4i * 4] = hh;
    };
    store4(a0, lane);
    store4(a1, 32 + lane);
    if (lane < 11) store4(a2, 64 + lane);
    if (lane < 20) Ah[orow + 300 + lane] = __float2half(0.f);
}

// single fused weight convert: all 5 weights -> contiguous fp16 planes.
// segments: 0..3 = Wr/Wc/Wrs/Wcs (K=300, KP=320), 4 = Wm (K=600, KP=640)
__global__ void wconv_all_kernel(const float* __restrict__ Wr, const float* __restrict__ Wc,
                                 const float* __restrict__ Wrs, const float* __restrict__ Wcs,
                                 const float* __restrict__ Wm) {
    int idx = blockIdx.x * blockDim.x + threadIdx.x;
    const int TOT = 4 * WPL + KPM * NP;    // 614400
    if (idx >= TOT) return;
    const float* W;
    int local, K;
    if (idx < 4 * WPL) {
        int seg = idx / WPL;
        local = idx - seg * WPL;
        W = (seg == 0) ? Wr : (seg == 1) ? Wc : (seg == 2) ? Wrs : Wcs;
        K = DD;
    } else {
        local = idx - 4 * WPL;
        W = Wm;
        K = 2 * DD;
    }
    int k = local / NP;
    int n = local - k * NP;
    float v = (k < K && n < DD) ? W[(size_t)k * DD + n] : 0.f;
    g_W[idx] = __float2half(v);
}

// ====== Tensor-core GEMM: fp16 single-pass, SW128, GBK=64, 4-stage ==========
// mode 0: fp32 out (guarded). mode 1: fp16 plane, zero-fill full padded tile.
// mode 2: fp16 out, store ONLY valid elements (for aliased mrg halves).
#define GBM 128
#define GBN 64
#define GBK 64
#define A_PL 16384u
#define B_PL 8192u
#define STG (A_PL + B_PL)           // 24576
#define NSTAGE 4
#define SMEM_GEMM (NSTAGE * STG)    // 98304

__global__ __launch_bounds__(256) void gemm_tc2_kernel(
    const fp16* __restrict__ Ap, int lda,
    const fp16* __restrict__ Bp,
    const float* __restrict__ bias,
    int M, int Ncols, int nK, int mode, int relu,
    float* __restrict__ Cf, int ldc,
    fp16* __restrict__ Ch, int ldcp)
{
    extern __shared__ __align__(128) char smem[];
    const uint32_t sb = (uint32_t)__cvta_generic_to_shared(smem);

    const int t = threadIdx.x;
    const int wid = t >> 5;
    const int lane = t & 31;
    const int warp_m = wid >> 1;
    const int warp_n = wid & 1;
    const int m0 = blockIdx.y * GBM;
    const int n0 = blockIdx.x * GBN;

    float acc[2][4][4];
    #pragma unroll
    for (int mi = 0; mi < 2; mi++)
        #pragma unroll
        for (int ni = 0; ni < 4; ni++)
            #pragma unroll
            for (int j = 0; j < 4; j++) acc[mi][ni][j] = 0.f;

    auto load_stage = [&](int stage, int k0) {
        const uint32_t base = sb + (uint32_t)stage * STG;
        const uint32_t aA = base;
        const uint32_t aB = base + A_PL;
        #pragma unroll
        for (int i = 0; i < 4; i++) {
            int idx = i * 256 + t;
            int r = idx >> 3, c = idx & 7;
            uint32_t d = SWZ((uint32_t)(r * 128 + c * 16));
            cp16(aA + d, Ap + (size_t)(m0 + r) * lda + k0 + c * 8);
        }
        #pragma unroll
        for (int i = 0; i < 2; i++) {
            int idx = i * 256 + t;
            int r = idx >> 3, c = idx & 7;
            uint32_t d = SWZ((uint32_t)(r * 128 + c * 16));
            cp16(aB + d, Bp + (size_t)(k0 + r) * NP + n0 + c * 8);
        }
        asm volatile("cp.async.commit_group;");
    };

    // prologue: three stages in flight
    load_stage(0, 0);
    if (nK > 1) load_stage(1, GBK);
    if (nK > 2) load_stage(2, 2 * GBK);

    const int lrow = lane & 15;
    const int lhi = lane >> 4;

    int stage = 0;
    for (int kt = 0; kt < nK; kt++) {
        if (kt + 3 < nK) {
            int s3 = stage + 3; if (s3 >= NSTAGE) s3 -= NSTAGE;
            load_stage(s3, (kt + 3) * GBK);
            asm volatile("cp.async.wait_group 3;");
        } else if (kt + 2 < nK) {
            asm volatile("cp.async.wait_group 2;");
        } else if (kt + 1 < nK) {
            asm volatile("cp.async.wait_group 1;");
        } else {
            asm volatile("cp.async.wait_group 0;");
        }
        __syncthreads();

        const uint32_t base = sb + (uint32_t)stage * STG;
        const uint32_t aA = base;
        const uint32_t aB = base + A_PL;

        #pragma unroll
        for (int ks = 0; ks < 4; ks++) {
            uint32_t ah[2][4];
            #pragma unroll
            for (int mi = 0; mi < 2; mi++) {
                int row = warp_m * 32 + mi * 16 + lrow;
                uint32_t off = SWZ((uint32_t)(row * 128 + ks * 32 + lhi * 16));
                ldsm_x4(ah[mi][0], ah[mi][1], ah[mi][2], ah[mi][3], aA + off);
            }
            uint32_t bh[4][2];
            #pragma unroll
            for (int nj = 0; nj < 2; nj++) {
                int krow = ks * 16 + lrow;
                uint32_t off = SWZ((uint32_t)(krow * 128 + warp_n * 64 + nj * 32 + lhi * 16));
                uint32_t r0, r1, r2, r3;
                ldsm_x4_t(r0, r1, r2, r3, aB + off);
                bh[nj * 2 + 0][0] = r0; bh[nj * 2 + 0][1] = r1;
                bh[nj * 2 + 1][0] = r2; bh[nj * 2 + 1][1] = r3;
            }
            #pragma unroll
            for (int mi = 0; mi < 2; mi++)
                #pragma unroll
                for (int ni = 0; ni < 4; ni++)
                    mma_fp16(acc[mi][ni], ah[mi], bh[ni]);
        }
        __syncthreads();
        stage++; if (stage >= NSTAGE) stage = 0;
    }

    // ---- epilogue ----
    const int g = lane >> 2;
    const int tig = lane & 3;
    #pragma unroll
    for (int mi = 0; mi < 2; mi++) {
        #pragma unroll
        for (int ni = 0; ni < 4; ni++) {
            int col = n0 + warp_n * 32 + ni * 8 + tig * 2;
            float bx = 0.f, by = 0.f;
            if (bias != nullptr && col < Ncols) {
                bx = bias[col];
                if (col + 1 < Ncols) by = bias[col + 1];
            }
            #pragma unroll
            for (int rr = 0; rr < 2; rr++) {
                int row = m0 + warp_m * 32 + mi * 16 + g + rr * 8;
                float vx = acc[mi][ni][rr * 2 + 0] + bx;
                float vy = acc[mi][ni][rr * 2 + 1] + by;
                if (relu) { vx = fmaxf(vx, 0.f); vy = fmaxf(vy, 0.f); }
                bool ok = (row < M) && (col < Ncols);
                if (mode == 0) {
                    if (ok)
                        *(float2*)(Cf + (size_t)row * ldc + col) = make_float2(vx, vy);
                } else if (mode == 1) {
                    if (!ok) { vx = 0.f; vy = 0.f; }
                    *(uint32_t*)&Ch[(size_t)row * ldcp + col] =
                        pack2(__float2half(vx), __float2half(vy));
                } else {
                    if (ok)
                        *(uint32_t*)&Ch[(size_t)row * ldcp + col] =
                            pack2(__float2half(vx), __float2half(vy));
                }
            }
        }
    }
}

// ---------------- LayerNorm (fp32, in place) --------------------------------
__global__ void ln_kernel(float* __restrict__ X, int ld,
                          const float* __restrict__ gamma,
                          const float* __restrict__ beta, int M) {
    int warp = (int)((blockIdx.x * (long)blockDim.x + threadIdx.x) >> 5);
    int lane = threadIdx.x & 31;
    if (warp >= M) return;
    float* p = X + (size_t)warp * ld;
    float v[10];
    float sum = 0.f;
    #pragma unroll
    for (int k = 0; k < 10; k++) {
        int c = lane + 32 * k;
        v[k] = (c < DD) ? p[c] : 0.f;
        sum += v[k];
    }
    #pragma unroll
    for (int o = 16; o > 0; o >>= 1) sum += __shfl_xor_sync(0xFFFFFFFFu, sum, o);
    float mu = sum * (1.f / DD);
    float var = 0.f;
    #pragma unroll
    for (int k = 0; k < 10; k++) {
        int c = lane + 32 * k;
        float d = (c < DD) ? (v[k] - mu) : 0.f;
        var += d * d;
    }
    #pragma unroll
    for (int o = 16; o > 0; o >>= 1) var += __shfl_xor_sync(0xFFFFFFFFu, var, o);
    float rsig = rsqrtf(var * (1.f / DD) + 1e-5f);
    #pragma unroll
    for (int k = 0; k < 10; k++) {
        int c = lane + 32 * k;
        if (c < DD) p[c] = (v[k] - mu) * rsig * gamma[c] + beta[c];
    }
}

// in-place LN on the two fp16 halves of each mrg row; zero pad cols [600,640)
__global__ void ln_mrg_kernel(const float* __restrict__ g0, const float* __restrict__ b0,
                              const float* __restrict__ g1, const float* __restrict__ b1) {
    int warp = (int)((blockIdx.x * (long)blockDim.x + threadIdx.x) >> 5);
    int lane = threadIdx.x & 31;
    if (warp >= NN) return;
    size_t orow = (size_t)warp * KPM;
    #pragma unroll
    for (int half = 0; half < 2; half++) {
        fp16* p = g_mrg + orow + half * DD;
        const float* gamma = half ? g1 : g0;
        const float* beta  = half ? b1 : b0;
        float v[10];
        float sum = 0.f;
        #pragma unroll
        for (int k = 0; k < 10; k++) {
            int c = lane + 32 * k;
            v[k] = (c < DD) ? __half2float(p[c]) : 0.f;
            sum += v[k];
        }
        #pragma unroll
        for (int o = 16; o > 0; o >>= 1) sum += __shfl_xor_sync(0xFFFFFFFFu, sum, o);
        float mu = sum * (1.f / DD);
        float var = 0.f;
        #pragma unroll
        for (int k = 0; k < 10; k++) {
            int c = lane + 32 * k;
            float d = (c < DD) ? (v[k] - mu) : 0.f;
            var += d * d;
        }
        #pragma unroll
        for (int o = 16; o > 0; o >>= 1) var += __shfl_xor_sync(0xFFFFFFFFu, var, o);
        float rsig = rsqrtf(var * (1.f / DD) + 1e-5f);
        #pragma unroll
        for (int k = 0; k < 10; k++) {
            int c = lane + 32 * k;
            if (c < DD)
                p[c] = __float2half((v[k] - mu) * rsig * gamma[c] + beta[c]);
        }
    }
    fp16 z = __float2half(0.f);
    g_mrg[orow + 600 + lane] = z;
    if (lane < 8) g_mrg[orow + 632 + lane] = z;
}

// ---------------- launch ----------------------------------------------------
extern "C" void kernel_launch(void* const* d_in, const int* in_sizes, int n_in,
                              void* d_out, int out_size) {
    const float* x    = (const float*)d_in[0];
    const int*   er   = (const int*)d_in[1];
    const int*   ec   = (const int*)d_in[2];
    const float* Wr   = (const float*)d_in[3];
    const float* br   = (const float*)d_in[4];
    const float* Wc   = (const float*)d_in[5];
    const float* bc   = (const float*)d_in[6];
    const float* Wrs  = (const float*)d_in[7];
    const float* brs  = (const float*)d_in[8];
    const float* g_rs = (const float*)d_in[9];
    const float* b_rs = (const float*)d_in[10];
    const float* Wcs  = (const float*)d_in[11];
    const float* bcs  = (const float*)d_in[12];
    const float* g_cs = (const float*)d_in[13];
    const float* b_cs = (const float*)d_in[14];
    const float* Wm   = (const float*)d_in[15];
    const float* bm   = (const float*)d_in[16];
    const float* g_m  = (const float*)d_in[17];
    const float* b_m  = (const float*)d_in[18];
    float* out = (float*)d_out;

    float* deg;
    cudaGetSymbolAddress((void**)&deg, g_deg);
    int *ideg, *off_r, *off_c, *cur_r, *cur_c, *csr_r, *csr_c;
    cudaGetSymbolAddress((void**)&ideg,  g_ideg);
    cudaGetSymbolAddress((void**)&off_r, g_off_r);
    cudaGetSymbolAddress((void**)&off_c, g_off_c);
    cudaGetSymbolAddress((void**)&cur_r, g_cur_r);
    cudaGetSymbolAddress((void**)&cur_c, g_cur_c);
    cudaGetSymbolAddress((void**)&csr_r, g_csr_r);
    cudaGetSymbolAddress((void**)&csr_c, g_csr_c);

    fp16 *aggr, *aggc, *rowg, *colg, *mrg, *pW;
    cudaGetSymbolAddress((void**)&aggr, g_aggr);
    cudaGetSymbolAddress((void**)&aggc, g_aggc);
    cudaGetSymbolAddress((void**)&rowg, g_rowg);
    cudaGetSymbolAddress((void**)&colg, g_colg);
    cudaGetSymbolAddress((void**)&mrg,  g_mrg);
    cudaGetSymbolAddress((void**)&pW,   g_W);
    fp16* pWr  = pW;
    fp16* pWc  = pW + WPL;
    fp16* pWrs = pW + 2 * WPL;
    fp16* pWcs = pW + 3 * WPL;
    fp16* pWm  = pW + 4 * WPL;

    cudaFuncSetAttribute(gemm_tc2_kernel,
                         cudaFuncAttributeMaxDynamicSharedMemorySize, SMEM_GEMM);

    // graph preprocessing (memsets replace zero kernels)
    cudaMemsetAsync(ideg, 0, 4 * NN * sizeof(int));
    cudaMemsetAsync(aggr + (size_t)NN * KP1, 0, (size_t)(MP - NN) * KP1 * sizeof(fp16));
    cudaMemsetAsync(aggc + (size_t)NN * KP1, 0, (size_t)(MP - NN) * KP1 * sizeof(fp16));
    cudaMemsetAsync(mrg  + (size_t)NN * KPM, 0, (size_t)(MP - NN) * KPM * sizeof(fp16));

    degree_kernel<<<(NE + 255) / 256, 256>>>(er, ec);
    normx_kernel<<<(int)(((long)NN * DD / 2 + 255) / 256), 256>>>((const float2*)x);
    dim3 sgrid(NSB, 2);
    scan1_kernel<<<sgrid, SB>>>();
    scan2_kernel<<<1, 256>>>(off_r, off_c);
    scan3_kernel<<<sgrid, SB>>>(off_r, cur_r, off_c, cur_c);
    dim3 fgrid((NE + 255) / 256, 2);
    fill2_kernel<<<fgrid, 256>>>(er, ec, cur_r, cur_c, csr_r, csr_c);
    dim3 ggrid2((NN * 32 + 255) / 256, 2);
    gather2_kernel<<<ggrid2, 256>>>(csr_r, csr_c, off_r, off_c, deg);

    // single fused weight convert
    const int WTOT = 4 * WPL + KPM * NP;
    wconv_all_kernel<<<(WTOT + 255) / 256, 256>>>(Wr, Wc, Wrs, Wcs, Wm);

    dim3 gg(NP / GBN, MP / GBM);   // (5, 782)
    const int nK1 = KP1 / GBK;     // 5
    const int nKm = KPM / GBK;     // 10

    // GraphConv GEMMs: relu -> fp16 planes (zero-filled padding)
    gemm_tc2_kernel<<<gg, 256, SMEM_GEMM>>>(aggr, KP1, pWr, br,
        NN, DD, nK1, 1, 1, nullptr, 0, rowg, KP1);
    gemm_tc2_kernel<<<gg, 256, SMEM_GEMM>>>(aggc, KP1, pWc, bc,
        NN, DD, nK1, 1, 1, nullptr, 0, colg, KP1);

    // support GEMMs -> fp16 mrg halves directly (mode 2: valid-only stores)
    gemm_tc2_kernel<<<gg, 256, SMEM_GEMM>>>(rowg, KP1, pWrs, brs,
        NN, DD, nK1, 2, 0, nullptr, 0, mrg, KPM);
    gemm_tc2_kernel<<<gg, 256, SMEM_GEMM>>>(colg, KP1, pWcs, bcs,
        NN, DD, nK1, 2, 0, nullptr, 0, mrg + DD, KPM);

    // in-place fp16 LN on both halves (+ zero pad cols)
    int lngrid = (NN + 7) / 8;
    ln_mrg_kernel<<<lngrid, 256>>>(g_rs, b_rs, g_cs, b_cs);

    // merge GEMM (K=640) -> fp32 out, then final LN
    gemm_tc2_kernel<<<gg, 256, SMEM_GEMM>>>(mrg, KPM, pWm, bm,
        NN, DD, nKm, 0, 0, out, DD, nullptr, 0);
    ln_kernel<<<lngrid, 256>>>(out, DD, g_m, b_m, NN);
}